// round 1
// baseline (speedup 1.0000x reference)
#include <cuda_runtime.h>

#define NN 50000
#define EE 500000
#define EPSF 1e-8f

typedef unsigned long long u64;

// ---------------- scratch (device globals; no allocations allowed) ----------------
__device__ __align__(16) float g_hedge[EE * 32];   // per-edge h_ij_edge
__device__ __align__(16) float g_expl[EE * 4];     // per-edge exp(logits)
__device__ __align__(16) float g_dir[EE * 4];      // dir.xyz, d
__device__ __align__(16) float g_denom[NN * 4];    // softmax denominators per head
__device__ __align__(16) float g_cnt[NN];          // neighbor counts
__device__ __align__(16) float g_sem[NN * 128];    // h_i_semantic accumulators
__device__ __align__(16) float g_comb[NN * 128];   // comb sums [c][x,y,z,pad]

// ---------------- helpers ----------------
__device__ __forceinline__ u64 pk2(float v) {
    u64 r; asm("mov.b64 %0,{%1,%1};" : "=l"(r) : "f"(v)); return r;
}
__device__ __forceinline__ void fma2(u64 &d, u64 a, u64 b) {
    asm("fma.rn.f32x2 %0,%1,%2,%0;" : "+l"(d) : "l"(a), "l"(b));
}
__device__ __forceinline__ float2 upk(u64 v) {
    float2 f; asm("mov.b64 {%0,%1},%2;" : "=f"(f.x), "=f"(f.y) : "l"(v)); return f;
}
__device__ __forceinline__ float silu_(float z) { return z * (1.f / (1.f + __expf(-z))); }
__device__ __forceinline__ void red4(float* p, float a, float b, float c, float d) {
    asm volatile("red.global.add.v4.f32 [%0], {%1,%2,%3,%4};"
                 :: "l"(p), "f"(a), "f"(b), "f"(c), "f"(d) : "memory");
}

// ---------------- K0: zero scratch ----------------
__global__ void k_zero() {
    int t = blockIdx.x * blockDim.x + threadIdx.x;
    int stride = gridDim.x * blockDim.x;
    float4 z = make_float4(0.f, 0.f, 0.f, 0.f);
    float4* p1 = (float4*)g_denom;
    for (int q = t; q < NN; q += stride) p1[q] = z;           // NN*4 floats
    float4* p2 = (float4*)g_cnt;
    for (int q = t; q < NN / 4; q += stride) p2[q] = z;
    float4* p3 = (float4*)g_sem;
    for (int q = t; q < NN * 32; q += stride) p3[q] = z;
    float4* p4 = (float4*)g_comb;
    for (int q = t; q < NN * 32; q += stride) p4[q] = z;
}

// ---------------- K1: edge pass 1 ----------------
// geometry, RBF, edge MLP (149->64->32), logits, exp, denom/count reductions
__global__ void __launch_bounds__(256) k_edge1(
    const float* __restrict__ h, const float* __restrict__ xx,
    const int* __restrict__ idx_i, const int* __restrict__ idx_j,
    const float* __restrict__ Win, const float* __restrict__ bin,
    const float* __restrict__ Wh,  const float* __restrict__ bh,
    const float* __restrict__ Wo,  const float* __restrict__ bo,
    const float* __restrict__ Wa,  const float* __restrict__ ba)
{
    __shared__ float sWh[149 * 64];    // 38144 B
    __shared__ float sWin[128 * 20];   // 10240 B
    for (int t = threadIdx.x; t < 149 * 64; t += 256) sWh[t] = Wh[t];
    for (int t = threadIdx.x; t < 128 * 20; t += 256) sWin[t] = Win[t];
    __syncthreads();

    int e = blockIdx.x * 256 + threadIdx.x;
    if (e >= EE) return;
    int i = idx_i[e], j = idx_j[e];

    float r0 = xx[3 * j]     - xx[3 * i];
    float r1 = xx[3 * j + 1] - xx[3 * i + 1];
    float r2 = xx[3 * j + 2] - xx[3 * i + 2];
    float d  = sqrtf(r0 * r0 + r1 * r1 + r2 * r2 + EPSF);
    float inv = 1.f / (d + EPSF);
    float dir0 = r0 * inv, dir1 = r1 * inv, dir2 = r2 * inv;

    u64 a64[32]; u64 a20[10];
    #pragma unroll
    for (int q = 0; q < 32; q++) a64[q] = 0ull;
    #pragma unroll
    for (int q = 0; q < 10; q++) a20[q] = 0ull;

    const float4* h4 = (const float4*)h;
    #pragma unroll
    for (int t = 0; t < 2; t++) {
        int node = (t == 0) ? i : j;
        int koff = t * 64;
        #pragma unroll 1
        for (int kk = 0; kk < 16; kk++) {
            float4 av = __ldg(&h4[node * 16 + kk]);
            float vv[4] = {av.x, av.y, av.z, av.w};
            #pragma unroll
            for (int u = 0; u < 4; u++) {
                int k = koff + kk * 4 + u;
                u64 hv = pk2(vv[u]);
                const u64* wr = (const u64*)&sWh[k * 64];
                #pragma unroll
                for (int q = 0; q < 32; q++) fma2(a64[q], hv, wr[q]);
                const u64* w2 = (const u64*)&sWin[k * 20];
                #pragma unroll
                for (int q = 0; q < 10; q++) fma2(a20[q], hv, w2[q]);
            }
        }
    }

    // PhysNet RBF * (h_cat @ W_edge_in + b_edge_in)  -> rows 128..147 of W_edge_h
    {
        float ed  = __expf(-d);
        const float mu0  = 0.6065306597126334f;          // exp(-0.5)
        const float dmu  = (1.f - mu0) / 19.f;
        const float bb   = 0.1f * (1.f - mu0);
        const float beta = 1.f / (bb * bb);
        float f20[20];
        #pragma unroll
        for (int q = 0; q < 10; q++) {
            float2 p = upk(a20[q]);
            f20[2 * q] = p.x; f20[2 * q + 1] = p.y;
        }
        #pragma unroll
        for (int r = 0; r < 20; r++) {
            float tt  = ed - (mu0 + r * dmu);
            float fil = __expf(-beta * tt * tt) * (f20[r] + __ldg(&bin[r]));
            u64 fv = pk2(fil);
            const u64* wr = (const u64*)&sWh[(128 + r) * 64];
            #pragma unroll
            for (int q = 0; q < 32; q++) fma2(a64[q], fv, wr[q]);
        }
        u64 dv2 = pk2(d);   // d / SCALE, SCALE = 1
        const u64* wr = (const u64*)&sWh[148 * 64];
        #pragma unroll
        for (int q = 0; q < 32; q++) fma2(a64[q], dv2, wr[q]);
    }

    // bias + silu -> hidden[64]; edge out: hidden @ W_edge_out[64,32] + b
    u64 ho[16];
    #pragma unroll
    for (int q = 0; q < 16; q++) ho[q] = 0ull;
    const u64* Wo8 = (const u64*)Wo;
    #pragma unroll
    for (int q = 0; q < 32; q++) {
        float2 p = upk(a64[q]);
        float z0 = silu_(p.x + __ldg(&bh[2 * q]));
        float z1 = silu_(p.y + __ldg(&bh[2 * q + 1]));
        u64 h0 = pk2(z0), h1 = pk2(z1);
        const u64* w0 = &Wo8[(2 * q) * 16];
        const u64* w1 = &Wo8[(2 * q + 1) * 16];
        #pragma unroll
        for (int c = 0; c < 16; c++) fma2(ho[c], h0, __ldg(&w0[c]));
        #pragma unroll
        for (int c = 0; c < 16; c++) fma2(ho[c], h1, __ldg(&w1[c]));
    }
    float he[32];
    #pragma unroll
    for (int q = 0; q < 16; q++) {
        float2 p = upk(ho[q]);
        he[2 * q]     = p.x + __ldg(&bo[2 * q]);
        he[2 * q + 1] = p.y + __ldg(&bo[2 * q + 1]);
    }

    // store h_edge
    float4* st = (float4*)&g_hedge[(size_t)e * 32];
    #pragma unroll
    for (int q = 0; q < 8; q++)
        st[q] = make_float4(he[4 * q], he[4 * q + 1], he[4 * q + 2], he[4 * q + 3]);

    // logits -> celu(alpha=2) -> exp
    float l0 = __ldg(&ba[0]), l1 = __ldg(&ba[1]), l2 = __ldg(&ba[2]), l3 = __ldg(&ba[3]);
    const float4* wa4 = (const float4*)Wa;
    #pragma unroll
    for (int c = 0; c < 32; c++) {
        float4 w = __ldg(&wa4[c]);
        l0 += he[c] * w.x; l1 += he[c] * w.y; l2 += he[c] * w.z; l3 += he[c] * w.w;
    }
    float e0 = __expf(l0 > 0.f ? l0 : 2.f * (__expf(0.5f * l0) - 1.f));
    float e1 = __expf(l1 > 0.f ? l1 : 2.f * (__expf(0.5f * l1) - 1.f));
    float e2 = __expf(l2 > 0.f ? l2 : 2.f * (__expf(0.5f * l2) - 1.f));
    float e3 = __expf(l3 > 0.f ? l3 : 2.f * (__expf(0.5f * l3) - 1.f));

    ((float4*)g_expl)[e] = make_float4(e0, e1, e2, e3);
    ((float4*)g_dir)[e]  = make_float4(dir0, dir1, dir2, d);
    red4(&g_denom[i * 4], e0, e1, e2, e3);
    atomicAdd(&g_cnt[i], 1.f);
}

// ---------------- K2: edge pass 2 ----------------
// attention normalize, semantic scatter, mix = tanh(sem @ W_x_mix), comb scatter
__global__ void __launch_bounds__(256) k_edge2(
    const int* __restrict__ idx_i, const float* __restrict__ Wx)
{
    __shared__ float sWx[128 * 32];   // 16 KB
    for (int t = threadIdx.x; t < 128 * 32; t += 256) sWx[t] = Wx[t];
    __syncthreads();

    int e = blockIdx.x * 256 + threadIdx.x;
    if (e >= EE) return;
    int i = idx_i[e];

    float4 ex = ((const float4*)g_expl)[e];
    float4 dn = *(const float4*)&g_denom[i * 4];
    float at[4] = { ex.x / (dn.x + EPSF), ex.y / (dn.y + EPSF),
                    ex.z / (dn.z + EPSF), ex.w / (dn.w + EPSF) };

    float he[32];
    const float4* hb = (const float4*)&g_hedge[(size_t)e * 32];
    #pragma unroll
    for (int q = 0; q < 8; q++) {
        float4 t = hb[q];
        he[4 * q] = t.x; he[4 * q + 1] = t.y; he[4 * q + 2] = t.z; he[4 * q + 3] = t.w;
    }

    u64 mx[16];
    #pragma unroll
    for (int q = 0; q < 16; q++) mx[q] = 0ull;

    float* sembase = &g_sem[(size_t)i * 128];
    #pragma unroll
    for (int kk = 0; kk < 32; kk++) {
        float s[4];
        #pragma unroll
        for (int u = 0; u < 4; u++) {
            int k = kk * 4 + u;
            s[u] = at[k >> 5] * he[k & 31];
            u64 s2 = pk2(s[u]);
            const u64* wr = (const u64*)&sWx[k * 32];
            #pragma unroll
            for (int q = 0; q < 16; q++) fma2(mx[q], s2, wr[q]);
        }
        red4(sembase + kk * 4, s[0], s[1], s[2], s[3]);
    }

    float4 dr = ((const float4*)g_dir)[e];
    float* cbase = &g_comb[(size_t)i * 128];
    #pragma unroll
    for (int q = 0; q < 16; q++) {
        float2 p = upk(mx[q]);
        float m0 = tanhf(p.x), m1 = tanhf(p.y);
        red4(cbase + (2 * q) * 4,     dr.x * m0, dr.y * m0, dr.z * m0, 0.f);
        red4(cbase + (2 * q + 1) * 4, dr.x * m1, dr.y * m1, dr.z * m1, 0.f);
    }
}

// ---------------- K3: node pass ----------------
__global__ void __launch_bounds__(64) k_node(
    const float* __restrict__ h, const float* __restrict__ xx, const float* __restrict__ vv,
    const float* __restrict__ W1,  const float* __restrict__ b1,
    const float* __restrict__ W2,  const float* __restrict__ b2,
    const float* __restrict__ Wp1, const float* __restrict__ bp1,
    const float* __restrict__ Wp2, const float* __restrict__ bp2,
    const float* __restrict__ Wv1, const float* __restrict__ bv1,
    const float* __restrict__ Wv2, const float* __restrict__ wvm,
    float* __restrict__ out)
{
    __shared__ float sh[64 * 165];   // stride 165 (odd*tid) -> conflict-free
    int i = blockIdx.x * 64 + threadIdx.x;
    if (i >= NN) return;
    float* my = &sh[threadIdx.x * 165];

    float invc = 1.f / fmaxf(g_cnt[i], 1.f);
    float n2[32];
    float dv0 = 0.f, dv1 = 0.f, dv2 = 0.f;
    const float4* cb = (const float4*)&g_comb[(size_t)i * 128];
    #pragma unroll
    for (int c = 0; c < 32; c++) {
        float4 q = cb[c];
        float ax = q.x * invc, ay = q.y * invc, az = q.z * invc;
        n2[c] = ax * ax + ay * ay + az * az;
        float w = __ldg(&wvm[c]);
        dv0 += ax * w; dv1 += ay * w; dv2 += az * w;
    }

    // spatial layer 1: n2[32] @ W_post1[32,64] + b -> silu -> my[0..63]
    {
        float t1[64];
        #pragma unroll
        for (int jj = 0; jj < 64; jj++) t1[jj] = __ldg(&bp1[jj]);
        #pragma unroll
        for (int c = 0; c < 32; c++) {
            float nv = n2[c];
            const float4* w = (const float4*)&Wp1[c * 64];
            #pragma unroll
            for (int q = 0; q < 16; q++) {
                float4 ww = __ldg(&w[q]);
                t1[4 * q] += nv * ww.x; t1[4 * q + 1] += nv * ww.y;
                t1[4 * q + 2] += nv * ww.z; t1[4 * q + 3] += nv * ww.w;
            }
        }
        #pragma unroll
        for (int jj = 0; jj < 64; jj++) my[jj] = silu_(t1[jj]);
    }
    // spatial layer 2: [64] @ W_post2[64,32] + b -> silu -> my[128..159]
    {
        u64 acc[16];
        #pragma unroll
        for (int q = 0; q < 16; q++) acc[q] = 0ull;
        #pragma unroll 1
        for (int k = 0; k < 64; k++) {
            u64 hv = pk2(my[k]);
            const u64* w = (const u64*)&Wp2[k * 32];
            #pragma unroll
            for (int q = 0; q < 16; q++) fma2(acc[q], hv, __ldg(&w[q]));
        }
        #pragma unroll
        for (int q = 0; q < 16; q++) {
            float2 p = upk(acc[q]);
            my[128 + 2 * q]     = silu_(p.x + __ldg(&bp2[2 * q]));
            my[128 + 2 * q + 1] = silu_(p.y + __ldg(&bp2[2 * q + 1]));
        }
    }

    // node layer 1: [h(64), sem(128), spatial(32)] @ W_node1[224,128] -> silu -> my[0..127]
    const float* hr = &h[(size_t)i * 64];
    const float* sr = &g_sem[(size_t)i * 128];
    #pragma unroll 1
    for (int ch = 0; ch < 4; ch++) {
        u64 acc[16];
        #pragma unroll
        for (int q = 0; q < 16; q++) acc[q] = 0ull;
        #pragma unroll 1
        for (int k = 0; k < 64; k++) {
            u64 hv = pk2(__ldg(&hr[k]));
            const u64* w = (const u64*)&W1[k * 128 + ch * 32];
            #pragma unroll
            for (int q = 0; q < 16; q++) fma2(acc[q], hv, __ldg(&w[q]));
        }
        #pragma unroll 1
        for (int k = 0; k < 128; k++) {
            u64 hv = pk2(__ldg(&sr[k]));
            const u64* w = (const u64*)&W1[(64 + k) * 128 + ch * 32];
            #pragma unroll
            for (int q = 0; q < 16; q++) fma2(acc[q], hv, __ldg(&w[q]));
        }
        #pragma unroll 1
        for (int k = 0; k < 32; k++) {
            u64 hv = pk2(my[128 + k]);
            const u64* w = (const u64*)&W1[(192 + k) * 128 + ch * 32];
            #pragma unroll
            for (int q = 0; q < 16; q++) fma2(acc[q], hv, __ldg(&w[q]));
        }
        // stash silu'd results (in registers first, write after to avoid overwriting my[0..63]
        // while a later chunk still needs spatial at my[128..159] - disjoint, safe)
        #pragma unroll
        for (int q = 0; q < 16; q++) {
            float2 p = upk(acc[q]);
            my[ch * 32 + 2 * q]     = silu_(p.x + __ldg(&b1[ch * 32 + 2 * q]));
            my[ch * 32 + 2 * q + 1] = silu_(p.y + __ldg(&b1[ch * 32 + 2 * q + 1]));
        }
    }

    // node layer 2: [128] @ W_node2[128,64] + b -> silu -> residual
    float hu[64];
    {
        u64 acc[32];
        #pragma unroll
        for (int q = 0; q < 32; q++) acc[q] = 0ull;
        #pragma unroll 1
        for (int k = 0; k < 128; k++) {
            u64 hv = pk2(my[k]);
            const u64* w = (const u64*)&W2[k * 64];
            #pragma unroll
            for (int q = 0; q < 32; q++) fma2(acc[q], hv, __ldg(&w[q]));
        }
        #pragma unroll
        for (int q = 0; q < 32; q++) {
            float2 p = upk(acc[q]);
            hu[2 * q]     = __ldg(&hr[2 * q])     + silu_(p.x + __ldg(&b2[2 * q]));
            hu[2 * q + 1] = __ldg(&hr[2 * q + 1]) + silu_(p.y + __ldg(&b2[2 * q + 1]));
        }
    }
    // write h_upd, stash hu into smem for the gate matvec
    {
        float4* outh = (float4*)&out[(size_t)i * 64];
        #pragma unroll
        for (int q = 0; q < 16; q++) {
            outh[q] = make_float4(hu[4 * q], hu[4 * q + 1], hu[4 * q + 2], hu[4 * q + 3]);
        }
        #pragma unroll
        for (int jj = 0; jj < 64; jj++) my[jj] = hu[jj];
    }

    // gate = 2*sigmoid( silu(h_upd @ W_vel1 + b) @ W_vel2 )
    float gate;
    {
        u64 acc[16];
        #pragma unroll
        for (int q = 0; q < 16; q++) acc[q] = 0ull;
        #pragma unroll 1
        for (int k = 0; k < 64; k++) {
            u64 hv = pk2(my[k]);
            const u64* w = (const u64*)&Wv1[k * 32];
            #pragma unroll
            for (int q = 0; q < 16; q++) fma2(acc[q], hv, __ldg(&w[q]));
        }
        float g = 0.f;
        #pragma unroll
        for (int q = 0; q < 16; q++) {
            float2 p = upk(acc[q]);
            g += silu_(p.x + __ldg(&bv1[2 * q]))     * __ldg(&Wv2[2 * q]);
            g += silu_(p.y + __ldg(&bv1[2 * q + 1])) * __ldg(&Wv2[2 * q + 1]);
        }
        gate = 2.f * (1.f / (1.f + __expf(-g)));
    }

    // v_upd = gate*v + dv ; x_upd = x + v_upd
    float vx = gate * vv[3 * i]     + dv0;
    float vy = gate * vv[3 * i + 1] + dv1;
    float vz = gate * vv[3 * i + 2] + dv2;
    float xox = xx[3 * i]     + vx;
    float xoy = xx[3 * i + 1] + vy;
    float xoz = xx[3 * i + 2] + vz;
    float* outx = out + (size_t)NN * 64;
    float* outv = outx + (size_t)NN * 3;
    outx[3 * i] = xox; outx[3 * i + 1] = xoy; outx[3 * i + 2] = xoz;
    outv[3 * i] = vx;  outv[3 * i + 1] = vy;  outv[3 * i + 2] = vz;
}

// ---------------- launch ----------------
extern "C" void kernel_launch(void* const* d_in, const int* in_sizes, int n_in,
                              void* d_out, int out_size) {
    const float* h   = (const float*)d_in[0];
    const float* x   = (const float*)d_in[1];
    const float* v   = (const float*)d_in[2];
    const int*   ii  = (const int*)d_in[3];
    const int*   jj  = (const int*)d_in[4];
    const float* Win = (const float*)d_in[5];
    const float* bin = (const float*)d_in[6];
    const float* Wh  = (const float*)d_in[7];
    const float* bh  = (const float*)d_in[8];
    const float* Wo  = (const float*)d_in[9];
    const float* bo  = (const float*)d_in[10];
    const float* Wa  = (const float*)d_in[11];
    const float* ba  = (const float*)d_in[12];
    const float* Wx  = (const float*)d_in[13];
    const float* W1  = (const float*)d_in[14];
    const float* b1  = (const float*)d_in[15];
    const float* W2  = (const float*)d_in[16];
    const float* b2  = (const float*)d_in[17];
    const float* Wp1 = (const float*)d_in[18];
    const float* bp1 = (const float*)d_in[19];
    const float* Wp2 = (const float*)d_in[20];
    const float* bp2 = (const float*)d_in[21];
    const float* Wv1 = (const float*)d_in[22];
    const float* bv1 = (const float*)d_in[23];
    const float* Wv2 = (const float*)d_in[24];
    const float* wvm = (const float*)d_in[25];
    float* out = (float*)d_out;

    k_zero<<<2048, 256>>>();
    k_edge1<<<(EE + 255) / 256, 256>>>(h, x, ii, jj, Win, bin, Wh, bh, Wo, bo, Wa, ba);
    k_edge2<<<(EE + 255) / 256, 256>>>(ii, Wx);
    k_node<<<(NN + 63) / 64, 64>>>(h, x, v, W1, b1, W2, b2, Wp1, bp1, Wp2, bp2,
                                   Wv1, bv1, Wv2, wvm, out);
}

// round 2
// speedup vs baseline: 1.3451x; 1.3451x over previous
#include <cuda_runtime.h>

#define NN 50000
#define EE 500000
#define EPSF 1e-8f

typedef unsigned long long u64;

// ---------------- scratch (device globals; no allocations allowed) ----------------
__device__ __align__(16) float g_hedge[EE * 32];   // per-edge h_ij_edge
__device__ __align__(16) float g_expl[EE * 4];     // per-edge exp(logits)
__device__ __align__(16) float g_dir[EE * 4];      // dir.xyz, d
__device__ __align__(16) float g_denom[NN * 4];    // softmax denominators per head
__device__ __align__(16) float g_cnt[NN];          // neighbor counts
__device__ __align__(16) float g_sem[NN * 128];    // h_i_semantic accumulators
__device__ __align__(16) float g_comb[NN * 128];   // comb sums [c][x,y,z,pad]

// ---------------- helpers ----------------
__device__ __forceinline__ u64 pk2(float v) {
    u64 r; asm("mov.b64 %0,{%1,%1};" : "=l"(r) : "f"(v)); return r;
}
__device__ __forceinline__ void fma2(u64 &d, u64 a, u64 b) {
    asm("fma.rn.f32x2 %0,%1,%2,%0;" : "+l"(d) : "l"(a), "l"(b));
}
__device__ __forceinline__ float2 upk(u64 v) {
    float2 f; asm("mov.b64 {%0,%1},%2;" : "=f"(f.x), "=f"(f.y) : "l"(v)); return f;
}
__device__ __forceinline__ float silu_(float z) { return z * (1.f / (1.f + __expf(-z))); }
__device__ __forceinline__ void red4(float* p, float a, float b, float c, float d) {
    asm volatile("red.global.add.v4.f32 [%0], {%1,%2,%3,%4};"
                 :: "l"(p), "f"(a), "f"(b), "f"(c), "f"(d) : "memory");
}

// ---------------- K0: zero scratch ----------------
__global__ void k_zero() {
    int t = blockIdx.x * blockDim.x + threadIdx.x;
    int stride = gridDim.x * blockDim.x;
    float4 z = make_float4(0.f, 0.f, 0.f, 0.f);
    float4* p1 = (float4*)g_denom;
    for (int q = t; q < NN; q += stride) p1[q] = z;
    float4* p2 = (float4*)g_cnt;
    for (int q = t; q < NN / 4; q += stride) p2[q] = z;
    float4* p3 = (float4*)g_sem;
    for (int q = t; q < NN * 32; q += stride) p3[q] = z;
    float4* p4 = (float4*)g_comb;
    for (int q = t; q < NN * 32; q += stride) p4[q] = z;
}

// ---------------- K1: edge pass 1 (unchanged from R1) ----------------
__global__ void __launch_bounds__(256) k_edge1(
    const float* __restrict__ h, const float* __restrict__ xx,
    const int* __restrict__ idx_i, const int* __restrict__ idx_j,
    const float* __restrict__ Win, const float* __restrict__ bin,
    const float* __restrict__ Wh,  const float* __restrict__ bh,
    const float* __restrict__ Wo,  const float* __restrict__ bo,
    const float* __restrict__ Wa,  const float* __restrict__ ba)
{
    __shared__ float sWh[149 * 64];
    __shared__ float sWin[128 * 20];
    for (int t = threadIdx.x; t < 149 * 64; t += 256) sWh[t] = Wh[t];
    for (int t = threadIdx.x; t < 128 * 20; t += 256) sWin[t] = Win[t];
    __syncthreads();

    int e = blockIdx.x * 256 + threadIdx.x;
    if (e >= EE) return;
    int i = idx_i[e], j = idx_j[e];

    float r0 = xx[3 * j]     - xx[3 * i];
    float r1 = xx[3 * j + 1] - xx[3 * i + 1];
    float r2 = xx[3 * j + 2] - xx[3 * i + 2];
    float d  = sqrtf(r0 * r0 + r1 * r1 + r2 * r2 + EPSF);
    float inv = 1.f / (d + EPSF);
    float dir0 = r0 * inv, dir1 = r1 * inv, dir2 = r2 * inv;

    u64 a64[32]; u64 a20[10];
    #pragma unroll
    for (int q = 0; q < 32; q++) a64[q] = 0ull;
    #pragma unroll
    for (int q = 0; q < 10; q++) a20[q] = 0ull;

    const float4* h4 = (const float4*)h;
    #pragma unroll
    for (int t = 0; t < 2; t++) {
        int node = (t == 0) ? i : j;
        int koff = t * 64;
        #pragma unroll 1
        for (int kk = 0; kk < 16; kk++) {
            float4 av = __ldg(&h4[node * 16 + kk]);
            float vv[4] = {av.x, av.y, av.z, av.w};
            #pragma unroll
            for (int u = 0; u < 4; u++) {
                int k = koff + kk * 4 + u;
                u64 hv = pk2(vv[u]);
                const u64* wr = (const u64*)&sWh[k * 64];
                #pragma unroll
                for (int q = 0; q < 32; q++) fma2(a64[q], hv, wr[q]);
                const u64* w2 = (const u64*)&sWin[k * 20];
                #pragma unroll
                for (int q = 0; q < 10; q++) fma2(a20[q], hv, w2[q]);
            }
        }
    }

    {
        float ed  = __expf(-d);
        const float mu0  = 0.6065306597126334f;
        const float dmu  = (1.f - mu0) / 19.f;
        const float bb   = 0.1f * (1.f - mu0);
        const float beta = 1.f / (bb * bb);
        float f20[20];
        #pragma unroll
        for (int q = 0; q < 10; q++) {
            float2 p = upk(a20[q]);
            f20[2 * q] = p.x; f20[2 * q + 1] = p.y;
        }
        #pragma unroll
        for (int r = 0; r < 20; r++) {
            float tt  = ed - (mu0 + r * dmu);
            float fil = __expf(-beta * tt * tt) * (f20[r] + __ldg(&bin[r]));
            u64 fv = pk2(fil);
            const u64* wr = (const u64*)&sWh[(128 + r) * 64];
            #pragma unroll
            for (int q = 0; q < 32; q++) fma2(a64[q], fv, wr[q]);
        }
        u64 dv2 = pk2(d);
        const u64* wr = (const u64*)&sWh[148 * 64];
        #pragma unroll
        for (int q = 0; q < 32; q++) fma2(a64[q], dv2, wr[q]);
    }

    u64 ho[16];
    #pragma unroll
    for (int q = 0; q < 16; q++) ho[q] = 0ull;
    const u64* Wo8 = (const u64*)Wo;
    #pragma unroll
    for (int q = 0; q < 32; q++) {
        float2 p = upk(a64[q]);
        float z0 = silu_(p.x + __ldg(&bh[2 * q]));
        float z1 = silu_(p.y + __ldg(&bh[2 * q + 1]));
        u64 h0 = pk2(z0), h1 = pk2(z1);
        const u64* w0 = &Wo8[(2 * q) * 16];
        const u64* w1 = &Wo8[(2 * q + 1) * 16];
        #pragma unroll
        for (int c = 0; c < 16; c++) fma2(ho[c], h0, __ldg(&w0[c]));
        #pragma unroll
        for (int c = 0; c < 16; c++) fma2(ho[c], h1, __ldg(&w1[c]));
    }
    float he[32];
    #pragma unroll
    for (int q = 0; q < 16; q++) {
        float2 p = upk(ho[q]);
        he[2 * q]     = p.x + __ldg(&bo[2 * q]);
        he[2 * q + 1] = p.y + __ldg(&bo[2 * q + 1]);
    }

    float4* st = (float4*)&g_hedge[(size_t)e * 32];
    #pragma unroll
    for (int q = 0; q < 8; q++)
        st[q] = make_float4(he[4 * q], he[4 * q + 1], he[4 * q + 2], he[4 * q + 3]);

    float l0 = __ldg(&ba[0]), l1 = __ldg(&ba[1]), l2 = __ldg(&ba[2]), l3 = __ldg(&ba[3]);
    const float4* wa4 = (const float4*)Wa;
    #pragma unroll
    for (int c = 0; c < 32; c++) {
        float4 w = __ldg(&wa4[c]);
        l0 += he[c] * w.x; l1 += he[c] * w.y; l2 += he[c] * w.z; l3 += he[c] * w.w;
    }
    float e0 = __expf(l0 > 0.f ? l0 : 2.f * (__expf(0.5f * l0) - 1.f));
    float e1 = __expf(l1 > 0.f ? l1 : 2.f * (__expf(0.5f * l1) - 1.f));
    float e2 = __expf(l2 > 0.f ? l2 : 2.f * (__expf(0.5f * l2) - 1.f));
    float e3 = __expf(l3 > 0.f ? l3 : 2.f * (__expf(0.5f * l3) - 1.f));

    ((float4*)g_expl)[e] = make_float4(e0, e1, e2, e3);
    ((float4*)g_dir)[e]  = make_float4(dir0, dir1, dir2, d);
    red4(&g_denom[i * 4], e0, e1, e2, e3);
    atomicAdd(&g_cnt[i], 1.f);
}

// ---------------- K2: edge pass 2 (unchanged from R1) ----------------
__global__ void __launch_bounds__(256) k_edge2(
    const int* __restrict__ idx_i, const float* __restrict__ Wx)
{
    __shared__ float sWx[128 * 32];
    for (int t = threadIdx.x; t < 128 * 32; t += 256) sWx[t] = Wx[t];
    __syncthreads();

    int e = blockIdx.x * 256 + threadIdx.x;
    if (e >= EE) return;
    int i = idx_i[e];

    float4 ex = ((const float4*)g_expl)[e];
    float4 dn = *(const float4*)&g_denom[i * 4];
    float at[4] = { ex.x / (dn.x + EPSF), ex.y / (dn.y + EPSF),
                    ex.z / (dn.z + EPSF), ex.w / (dn.w + EPSF) };

    float he[32];
    const float4* hb = (const float4*)&g_hedge[(size_t)e * 32];
    #pragma unroll
    for (int q = 0; q < 8; q++) {
        float4 t = hb[q];
        he[4 * q] = t.x; he[4 * q + 1] = t.y; he[4 * q + 2] = t.z; he[4 * q + 3] = t.w;
    }

    u64 mx[16];
    #pragma unroll
    for (int q = 0; q < 16; q++) mx[q] = 0ull;

    float* sembase = &g_sem[(size_t)i * 128];
    #pragma unroll
    for (int kk = 0; kk < 32; kk++) {
        float s[4];
        #pragma unroll
        for (int u = 0; u < 4; u++) {
            int k = kk * 4 + u;
            s[u] = at[k >> 5] * he[k & 31];
            u64 s2 = pk2(s[u]);
            const u64* wr = (const u64*)&sWx[k * 32];
            #pragma unroll
            for (int q = 0; q < 16; q++) fma2(mx[q], s2, wr[q]);
        }
        red4(sembase + kk * 4, s[0], s[1], s[2], s[3]);
    }

    float4 dr = ((const float4*)g_dir)[e];
    float* cbase = &g_comb[(size_t)i * 128];
    #pragma unroll
    for (int q = 0; q < 16; q++) {
        float2 p = upk(mx[q]);
        float m0 = tanhf(p.x), m1 = tanhf(p.y);
        red4(cbase + (2 * q) * 4,     dr.x * m0, dr.y * m0, dr.z * m0, 0.f);
        red4(cbase + (2 * q + 1) * 4, dr.x * m1, dr.y * m1, dr.z * m1, 0.f);
    }
}

// ---------------- K3: node pass v2 ----------------
// 256 threads/block, 1 node/thread, ALL weights in dynamic smem (168KB),
// intermediates fully register-resident with fused layer-pair accumulation.
__global__ void __launch_bounds__(256, 1) k_node(
    const float* __restrict__ h, const float* __restrict__ xx, const float* __restrict__ vv,
    const float* __restrict__ W1,  const float* __restrict__ b1,
    const float* __restrict__ W2,  const float* __restrict__ b2,
    const float* __restrict__ Wp1, const float* __restrict__ bp1,
    const float* __restrict__ Wp2, const float* __restrict__ bp2,
    const float* __restrict__ Wv1, const float* __restrict__ bv1,
    const float* __restrict__ Wv2, const float* __restrict__ wvm,
    float* __restrict__ out)
{
    extern __shared__ float sw[];
    float* sW1  = sw;              // 224*128 = 28672
    float* sW2  = sw + 28672;      // 128*64  =  8192
    float* sWp1 = sW2 + 8192;      // 32*64   =  2048
    float* sWp2 = sWp1 + 2048;     // 64*32   =  2048
    float* sWv1 = sWp2 + 2048;     // 64*32   =  2048

    {
        float4* d = (float4*)sw;
        const float4* s = (const float4*)W1;
        for (int t = threadIdx.x; t < 28672 / 4; t += 256) d[t] = s[t];
        d = (float4*)sW2; s = (const float4*)W2;
        for (int t = threadIdx.x; t < 8192 / 4; t += 256) d[t] = s[t];
        d = (float4*)sWp1; s = (const float4*)Wp1;
        for (int t = threadIdx.x; t < 2048 / 4; t += 256) d[t] = s[t];
        d = (float4*)sWp2; s = (const float4*)Wp2;
        for (int t = threadIdx.x; t < 2048 / 4; t += 256) d[t] = s[t];
        d = (float4*)sWv1; s = (const float4*)Wv1;
        for (int t = threadIdx.x; t < 2048 / 4; t += 256) d[t] = s[t];
    }
    __syncthreads();

    int i = blockIdx.x * 256 + threadIdx.x;
    if (i >= NN) return;

    // ---- comb -> n2 + dv ----
    float invc = 1.f / fmaxf(g_cnt[i], 1.f);
    float n2[32];
    float dv0 = 0.f, dv1 = 0.f, dv2 = 0.f;
    const float4* cb = (const float4*)&g_comb[(size_t)i * 128];
    #pragma unroll
    for (int c = 0; c < 32; c++) {
        float4 q = cb[c];
        float ax = q.x * invc, ay = q.y * invc, az = q.z * invc;
        n2[c] = ax * ax + ay * ay + az * az;
        float w = __ldg(&wvm[c]);
        dv0 += ax * w; dv1 += ay * w; dv2 += az * w;
    }

    // ---- spatial MLP, layer1 -> layer2 fused ----
    float spa[32];
    {
        u64 s2acc[16];
        #pragma unroll
        for (int q = 0; q < 16; q++) s2acc[q] = 0ull;

        #pragma unroll 1
        for (int half = 0; half < 2; half++) {
            u64 acc[16];
            #pragma unroll
            for (int q = 0; q < 16; q++) acc[q] = 0ull;
            #pragma unroll 4
            for (int k = 0; k < 32; k++) {
                u64 nv = pk2(n2[k]);
                const u64* w = (const u64*)&sWp1[k * 64 + half * 32];
                #pragma unroll
                for (int q = 0; q < 16; q++) fma2(acc[q], nv, w[q]);
            }
            #pragma unroll 2
            for (int q = 0; q < 16; q++) {
                float2 p = upk(acc[q]);
                int row = half * 32 + 2 * q;
                float z0 = silu_(p.x + __ldg(&bp1[row]));
                float z1 = silu_(p.y + __ldg(&bp1[row + 1]));
                u64 a0 = pk2(z0), a1 = pk2(z1);
                const u64* w0 = (const u64*)&sWp2[row * 32];
                const u64* w1 = w0 + 16;
                #pragma unroll
                for (int c = 0; c < 16; c++) fma2(s2acc[c], a0, w0[c]);
                #pragma unroll
                for (int c = 0; c < 16; c++) fma2(s2acc[c], a1, w1[c]);
            }
        }
        #pragma unroll
        for (int q = 0; q < 16; q++) {
            float2 p = upk(s2acc[q]);
            spa[2 * q]     = silu_(p.x + __ldg(&bp2[2 * q]));
            spa[2 * q + 1] = silu_(p.y + __ldg(&bp2[2 * q + 1]));
        }
    }

    // ---- node MLP: layer1 (224->128) -> layer2 (128->64) fused ----
    u64 acc2[32];
    #pragma unroll
    for (int q = 0; q < 32; q++) acc2[q] = 0ull;

    const float4* h4 = (const float4*)(h + (size_t)i * 64);
    const float4* s4 = (const float4*)&g_sem[(size_t)i * 128];

    #pragma unroll 1
    for (int half = 0; half < 2; half++) {
        int co = half * 64;   // output columns [co, co+64)
        u64 acc[32];
        #pragma unroll
        for (int q = 0; q < 32; q++) acc[q] = 0ull;

        // h rows 0..63
        #pragma unroll 1
        for (int k4 = 0; k4 < 16; k4++) {
            float4 hv = __ldg(&h4[k4]);
            float hvv[4] = {hv.x, hv.y, hv.z, hv.w};
            #pragma unroll
            for (int u = 0; u < 4; u++) {
                u64 a = pk2(hvv[u]);
                const u64* w = (const u64*)&sW1[(k4 * 4 + u) * 128 + co];
                #pragma unroll
                for (int q = 0; q < 32; q++) fma2(acc[q], a, w[q]);
            }
        }
        // sem rows 64..191
        #pragma unroll 1
        for (int k4 = 0; k4 < 32; k4++) {
            float4 sv = __ldg(&s4[k4]);
            float svv[4] = {sv.x, sv.y, sv.z, sv.w};
            #pragma unroll
            for (int u = 0; u < 4; u++) {
                u64 a = pk2(svv[u]);
                const u64* w = (const u64*)&sW1[(64 + k4 * 4 + u) * 128 + co];
                #pragma unroll
                for (int q = 0; q < 32; q++) fma2(acc[q], a, w[q]);
            }
        }
        // spatial rows 192..223
        #pragma unroll 2
        for (int k = 0; k < 32; k++) {
            u64 a = pk2(spa[k]);
            const u64* w = (const u64*)&sW1[(192 + k) * 128 + co];
            #pragma unroll
            for (int q = 0; q < 32; q++) fma2(acc[q], a, w[q]);
        }
        // activation + fused accumulation into layer2
        #pragma unroll 1
        for (int q = 0; q < 32; q++) {
            float2 p = upk(acc[q]);
            int row = co + 2 * q;
            float z0 = silu_(p.x + __ldg(&b1[row]));
            float z1 = silu_(p.y + __ldg(&b1[row + 1]));
            u64 a0 = pk2(z0), a1 = pk2(z1);
            const u64* w0 = (const u64*)&sW2[row * 64];
            const u64* w1 = w0 + 32;
            #pragma unroll
            for (int c = 0; c < 32; c++) fma2(acc2[c], a0, w0[c]);
            #pragma unroll
            for (int c = 0; c < 32; c++) fma2(acc2[c], a1, w1[c]);
        }
    }

    // ---- residual + write h_upd ----
    const float* hr = h + (size_t)i * 64;
    float hu[64];
    #pragma unroll
    for (int q = 0; q < 32; q++) {
        float2 p = upk(acc2[q]);
        hu[2 * q]     = __ldg(&hr[2 * q])     + silu_(p.x + __ldg(&b2[2 * q]));
        hu[2 * q + 1] = __ldg(&hr[2 * q + 1]) + silu_(p.y + __ldg(&b2[2 * q + 1]));
    }
    {
        float4* outh = (float4*)&out[(size_t)i * 64];
        #pragma unroll
        for (int q = 0; q < 16; q++)
            outh[q] = make_float4(hu[4 * q], hu[4 * q + 1], hu[4 * q + 2], hu[4 * q + 3]);
    }

    // ---- gate ----
    float gate;
    {
        u64 ga[16];
        #pragma unroll
        for (int q = 0; q < 16; q++) ga[q] = 0ull;
        #pragma unroll 4
        for (int k = 0; k < 64; k++) {
            u64 a = pk2(hu[k]);
            const u64* w = (const u64*)&sWv1[k * 32];
            #pragma unroll
            for (int q = 0; q < 16; q++) fma2(ga[q], a, w[q]);
        }
        float g = 0.f;
        #pragma unroll
        for (int q = 0; q < 16; q++) {
            float2 p = upk(ga[q]);
            g += silu_(p.x + __ldg(&bv1[2 * q]))     * __ldg(&Wv2[2 * q]);
            g += silu_(p.y + __ldg(&bv1[2 * q + 1])) * __ldg(&Wv2[2 * q + 1]);
        }
        gate = 2.f * (1.f / (1.f + __expf(-g)));
    }

    // ---- v_upd / x_upd ----
    float vx = gate * vv[3 * i]     + dv0;
    float vy = gate * vv[3 * i + 1] + dv1;
    float vz = gate * vv[3 * i + 2] + dv2;
    float* outx = out + (size_t)NN * 64;
    float* outv = outx + (size_t)NN * 3;
    outx[3 * i] = xx[3 * i]     + vx;
    outx[3 * i + 1] = xx[3 * i + 1] + vy;
    outx[3 * i + 2] = xx[3 * i + 2] + vz;
    outv[3 * i] = vx;  outv[3 * i + 1] = vy;  outv[3 * i + 2] = vz;
}

// ---------------- launch ----------------
extern "C" void kernel_launch(void* const* d_in, const int* in_sizes, int n_in,
                              void* d_out, int out_size) {
    const float* h   = (const float*)d_in[0];
    const float* x   = (const float*)d_in[1];
    const float* v   = (const float*)d_in[2];
    const int*   ii  = (const int*)d_in[3];
    const int*   jj  = (const int*)d_in[4];
    const float* Win = (const float*)d_in[5];
    const float* bin = (const float*)d_in[6];
    const float* Wh  = (const float*)d_in[7];
    const float* bh  = (const float*)d_in[8];
    const float* Wo  = (const float*)d_in[9];
    const float* bo  = (const float*)d_in[10];
    const float* Wa  = (const float*)d_in[11];
    const float* ba  = (const float*)d_in[12];
    const float* Wx  = (const float*)d_in[13];
    const float* W1  = (const float*)d_in[14];
    const float* b1  = (const float*)d_in[15];
    const float* W2  = (const float*)d_in[16];
    const float* b2  = (const float*)d_in[17];
    const float* Wp1 = (const float*)d_in[18];
    const float* bp1 = (const float*)d_in[19];
    const float* Wp2 = (const float*)d_in[20];
    const float* bp2 = (const float*)d_in[21];
    const float* Wv1 = (const float*)d_in[22];
    const float* bv1 = (const float*)d_in[23];
    const float* Wv2 = (const float*)d_in[24];
    const float* wvm = (const float*)d_in[25];
    float* out = (float*)d_out;

    const int NODE_SMEM = 43008 * 4;  // 172032 B dynamic smem for k_node
    // Idempotent; if it no-ops during graph capture the attribute is already set
    // from the correctness-run call.
    cudaFuncSetAttribute(k_node, cudaFuncAttributeMaxDynamicSharedMemorySize, NODE_SMEM);

    k_zero<<<2048, 256>>>();
    k_edge1<<<(EE + 255) / 256, 256>>>(h, x, ii, jj, Win, bin, Wh, bh, Wo, bo, Wa, ba);
    k_edge2<<<(EE + 255) / 256, 256>>>(ii, Wx);
    k_node<<<(NN + 255) / 256, 256, NODE_SMEM>>>(h, x, v, W1, b1, W2, b2, Wp1, bp1, Wp2, bp2,
                                                 Wv1, bv1, Wv2, wvm, out);
}

// round 3
// speedup vs baseline: 1.7686x; 1.3149x over previous
#include <cuda_runtime.h>

#define NN 50000
#define EE 500000
#define EPSF 1e-8f

typedef unsigned long long u64;

// ---------------- scratch (device globals) ----------------
__device__ __align__(16) float g_hedge[EE * 32];
__device__ __align__(16) float g_expl[EE * 4];
__device__ __align__(16) float g_dir[EE * 4];
__device__ __align__(16) float g_denom[NN * 4];
__device__ __align__(16) float g_cnt[NN];
__device__ __align__(16) float g_sem[NN * 128];    // UNNORMALIZED exp*he sums
__device__ __align__(16) float g_comb[NN * 96];    // packed [c*3+axis]
__device__ __align__(16) float g_P1[NN * 64];      // h @ Wh[0:64]
__device__ __align__(16) float g_P2[NN * 64];      // h @ Wh[64:128]
__device__ __align__(16) float g_Q1[NN * 20];      // h @ Win[0:64] + bin
__device__ __align__(16) float g_Q2[NN * 20];      // h @ Win[64:128]

// ---------------- helpers ----------------
__device__ __forceinline__ u64 pk2(float v) {
    u64 r; asm("mov.b64 %0,{%1,%1};" : "=l"(r) : "f"(v)); return r;
}
__device__ __forceinline__ u64 pk(float a, float b) {
    u64 r; asm("mov.b64 %0,{%1,%2};" : "=l"(r) : "f"(a), "f"(b)); return r;
}
__device__ __forceinline__ void fma2(u64 &d, u64 a, u64 b) {
    asm("fma.rn.f32x2 %0,%1,%2,%0;" : "+l"(d) : "l"(a), "l"(b));
}
__device__ __forceinline__ float2 upk(u64 v) {
    float2 f; asm("mov.b64 {%0,%1},%2;" : "=f"(f.x), "=f"(f.y) : "l"(v)); return f;
}
__device__ __forceinline__ float silu_(float z) { return z * (1.f / (1.f + __expf(-z))); }
__device__ __forceinline__ void red4(float* p, float a, float b, float c, float d) {
    asm volatile("red.global.add.v4.f32 [%0], {%1,%2,%3,%4};"
                 :: "l"(p), "f"(a), "f"(b), "f"(c), "f"(d) : "memory");
}

// ---------------- K0: zero scratch ----------------
__global__ void k_zero() {
    int t = blockIdx.x * blockDim.x + threadIdx.x;
    int stride = gridDim.x * blockDim.x;
    float4 z = make_float4(0.f, 0.f, 0.f, 0.f);
    float4* p1 = (float4*)g_denom;
    for (int q = t; q < NN; q += stride) p1[q] = z;
    float4* p2 = (float4*)g_cnt;
    for (int q = t; q < NN / 4; q += stride) p2[q] = z;
    float4* p3 = (float4*)g_sem;
    for (int q = t; q < NN * 32; q += stride) p3[q] = z;
    float4* p4 = (float4*)g_comb;
    for (int q = t; q < NN * 24; q += stride) p4[q] = z;
}

// ---------------- K_pre: per-node projections ----------------
// P1 = h @ Wh[0:64], P2 = h @ Wh[64:128], Q1 = h @ Win[0:64] + bin, Q2 = h @ Win[64:128]
__global__ void __launch_bounds__(256) k_pre(
    const float* __restrict__ h,
    const float* __restrict__ Wh, const float* __restrict__ Win,
    const float* __restrict__ bin)
{
    __shared__ float sWh[128 * 64];   // 32 KB
    __shared__ float sWin[128 * 20];  // 10 KB
    for (int t = threadIdx.x; t < 128 * 64; t += 256) sWh[t] = Wh[t];
    for (int t = threadIdx.x; t < 128 * 20; t += 256) sWin[t] = Win[t];
    __syncthreads();

    int i = blockIdx.x * 256 + threadIdx.x;
    if (i >= NN) return;
    const float4* h4 = (const float4*)(h + (size_t)i * 64);

    #pragma unroll 1
    for (int g = 0; g < 2; g++) {
        u64 aP[32]; u64 aQ[10];
        #pragma unroll
        for (int q = 0; q < 32; q++) aP[q] = 0ull;
        #pragma unroll
        for (int q = 0; q < 10; q++) aQ[q] = 0ull;
        #pragma unroll 2
        for (int k4 = 0; k4 < 16; k4++) {
            float4 hv = __ldg(&h4[k4]);
            float hvv[4] = {hv.x, hv.y, hv.z, hv.w};
            #pragma unroll
            for (int u = 0; u < 4; u++) {
                int k = g * 64 + k4 * 4 + u;
                u64 a = pk2(hvv[u]);
                const u64* wr = (const u64*)&sWh[k * 64];
                #pragma unroll
                for (int q = 0; q < 32; q++) fma2(aP[q], a, wr[q]);
                const u64* w2 = (const u64*)&sWin[k * 20];
                #pragma unroll
                for (int q = 0; q < 10; q++) fma2(aQ[q], a, w2[q]);
            }
        }
        float* P = (g == 0) ? &g_P1[(size_t)i * 64] : &g_P2[(size_t)i * 64];
        float* Q = (g == 0) ? &g_Q1[(size_t)i * 20] : &g_Q2[(size_t)i * 20];
        float4* P4 = (float4*)P;
        #pragma unroll
        for (int q = 0; q < 16; q++) {
            float2 p0 = upk(aP[2 * q]);
            float2 p1 = upk(aP[2 * q + 1]);
            P4[q] = make_float4(p0.x, p0.y, p1.x, p1.y);
        }
        #pragma unroll
        for (int q = 0; q < 10; q++) {
            float2 p = upk(aQ[q]);
            if (g == 0) {
                Q[2 * q]     = p.x + __ldg(&bin[2 * q]);
                Q[2 * q + 1] = p.y + __ldg(&bin[2 * q + 1]);
            } else {
                Q[2 * q] = p.x; Q[2 * q + 1] = p.y;
            }
        }
    }
}

// ---------------- K1: edge pass 1 ----------------
// geometry + RBF + (P1[i]+P2[j]+rbf rows+d row) -> silu -> Wo -> he, logits,
// exp, denom/cnt reductions, UNNORMALIZED semantic scatter
__global__ void __launch_bounds__(256) k_edge1(
    const float* __restrict__ xx,
    const int* __restrict__ idx_i, const int* __restrict__ idx_j,
    const float* __restrict__ Wh,  const float* __restrict__ bh,
    const float* __restrict__ Wo,  const float* __restrict__ bo,
    const float* __restrict__ Wa,  const float* __restrict__ ba)
{
    __shared__ float sWr[20 * 64];   // rbf rows 128..147
    __shared__ float sWl[64];        // row 148
    __shared__ float sWo[64 * 32];
    __shared__ float sWa[32 * 4];
    __shared__ float sbh[64], sbo[32], sba[4];
    for (int t = threadIdx.x; t < 20 * 64; t += 256) sWr[t] = Wh[128 * 64 + t];
    for (int t = threadIdx.x; t < 64; t += 256)      sWl[t] = Wh[148 * 64 + t];
    for (int t = threadIdx.x; t < 64 * 32; t += 256) sWo[t] = Wo[t];
    for (int t = threadIdx.x; t < 128; t += 256)     sWa[t] = Wa[t];
    if (threadIdx.x < 64) sbh[threadIdx.x] = bh[threadIdx.x];
    if (threadIdx.x < 32) sbo[threadIdx.x] = bo[threadIdx.x];
    if (threadIdx.x < 4)  sba[threadIdx.x] = ba[threadIdx.x];
    __syncthreads();

    int e = blockIdx.x * 256 + threadIdx.x;
    if (e >= EE) return;
    int i = idx_i[e], j = idx_j[e];

    float r0 = __ldg(&xx[3 * j])     - __ldg(&xx[3 * i]);
    float r1 = __ldg(&xx[3 * j + 1]) - __ldg(&xx[3 * i + 1]);
    float r2 = __ldg(&xx[3 * j + 2]) - __ldg(&xx[3 * i + 2]);
    float d  = sqrtf(r0 * r0 + r1 * r1 + r2 * r2 + EPSF);
    float inv = 1.f / (d + EPSF);
    float dir0 = r0 * inv, dir1 = r1 * inv, dir2 = r2 * inv;

    // RBF filter values
    float f20[20];
    {
        const float4* q1 = (const float4*)&g_Q1[(size_t)i * 20];
        const float4* q2 = (const float4*)&g_Q2[(size_t)j * 20];
        float ed  = __expf(-d);
        const float mu0  = 0.6065306597126334f;
        const float dmu  = (1.f - mu0) / 19.f;
        const float bb   = 0.1f * (1.f - mu0);
        const float beta = 1.f / (bb * bb);
        #pragma unroll
        for (int q = 0; q < 5; q++) {
            float4 a = __ldg(&q1[q]);
            float4 b = __ldg(&q2[q]);
            float qs[4] = {a.x + b.x, a.y + b.y, a.z + b.z, a.w + b.w};
            #pragma unroll
            for (int u = 0; u < 4; u++) {
                int r = q * 4 + u;
                float tt = ed - (mu0 + r * dmu);
                f20[r] = __expf(-beta * tt * tt) * qs[u];
            }
        }
    }

    // pre-activation: P1[i] + P2[j] + rbf rows + d row
    u64 a64[32];
    {
        const float4* p1 = (const float4*)&g_P1[(size_t)i * 64];
        const float4* p2 = (const float4*)&g_P2[(size_t)j * 64];
        #pragma unroll
        for (int q = 0; q < 16; q++) {
            float4 a = __ldg(&p1[q]);
            float4 b = __ldg(&p2[q]);
            a64[2 * q]     = pk(a.x + b.x, a.y + b.y);
            a64[2 * q + 1] = pk(a.z + b.z, a.w + b.w);
        }
    }
    #pragma unroll 4
    for (int r = 0; r < 20; r++) {
        u64 fv = pk2(f20[r]);
        const u64* wr = (const u64*)&sWr[r * 64];
        #pragma unroll
        for (int q = 0; q < 32; q++) fma2(a64[q], fv, wr[q]);
    }
    {
        u64 dv2 = pk2(d);
        const u64* wr = (const u64*)sWl;
        #pragma unroll
        for (int q = 0; q < 32; q++) fma2(a64[q], dv2, wr[q]);
    }

    // bias + silu -> hidden[64]; hidden @ Wo + bo -> he[32]
    u64 ho[16];
    #pragma unroll
    for (int q = 0; q < 16; q++) ho[q] = 0ull;
    #pragma unroll 4
    for (int q = 0; q < 32; q++) {
        float2 p = upk(a64[q]);
        float z0 = silu_(p.x + sbh[2 * q]);
        float z1 = silu_(p.y + sbh[2 * q + 1]);
        u64 h0 = pk2(z0), h1 = pk2(z1);
        const u64* w0 = (const u64*)&sWo[(2 * q) * 32];
        const u64* w1 = w0 + 16;
        #pragma unroll
        for (int c = 0; c < 16; c++) fma2(ho[c], h0, w0[c]);
        #pragma unroll
        for (int c = 0; c < 16; c++) fma2(ho[c], h1, w1[c]);
    }
    float he[32];
    #pragma unroll
    for (int q = 0; q < 16; q++) {
        float2 p = upk(ho[q]);
        he[2 * q]     = p.x + sbo[2 * q];
        he[2 * q + 1] = p.y + sbo[2 * q + 1];
    }

    // store h_edge
    float4* st = (float4*)&g_hedge[(size_t)e * 32];
    #pragma unroll
    for (int q = 0; q < 8; q++)
        st[q] = make_float4(he[4 * q], he[4 * q + 1], he[4 * q + 2], he[4 * q + 3]);

    // logits -> celu(alpha=2) -> exp
    float l0 = sba[0], l1 = sba[1], l2 = sba[2], l3 = sba[3];
    const float4* wa4 = (const float4*)sWa;
    #pragma unroll
    for (int c = 0; c < 32; c++) {
        float4 w = wa4[c];
        l0 += he[c] * w.x; l1 += he[c] * w.y; l2 += he[c] * w.z; l3 += he[c] * w.w;
    }
    float eArr[4];
    eArr[0] = __expf(l0 > 0.f ? l0 : 2.f * (__expf(0.5f * l0) - 1.f));
    eArr[1] = __expf(l1 > 0.f ? l1 : 2.f * (__expf(0.5f * l1) - 1.f));
    eArr[2] = __expf(l2 > 0.f ? l2 : 2.f * (__expf(0.5f * l2) - 1.f));
    eArr[3] = __expf(l3 > 0.f ? l3 : 2.f * (__expf(0.5f * l3) - 1.f));

    ((float4*)g_expl)[e] = make_float4(eArr[0], eArr[1], eArr[2], eArr[3]);
    ((float4*)g_dir)[e]  = make_float4(dir0, dir1, dir2, d);
    red4(&g_denom[i * 4], eArr[0], eArr[1], eArr[2], eArr[3]);
    atomicAdd(&g_cnt[i], 1.f);

    // UNNORMALIZED semantic scatter: sem[i][h*32+b] += exp[h]*he[b]
    float* sembase = &g_sem[(size_t)i * 128];
    #pragma unroll
    for (int kk = 0; kk < 32; kk++) {
        float eh = eArr[kk >> 3];
        int b0 = (4 * kk) & 31;
        red4(sembase + 4 * kk, eh * he[b0], eh * he[b0 + 1], eh * he[b0 + 2], eh * he[b0 + 3]);
    }
}

// ---------------- K2: edge pass 2 ----------------
// att normalize, mix = tanh(sem_edge @ Wx), packed comb scatter (24 red4)
__global__ void __launch_bounds__(256) k_edge2(
    const int* __restrict__ idx_i, const float* __restrict__ Wx)
{
    __shared__ float sWx[128 * 32];
    for (int t = threadIdx.x; t < 128 * 32; t += 256) sWx[t] = Wx[t];
    __syncthreads();

    int e = blockIdx.x * 256 + threadIdx.x;
    if (e >= EE) return;
    int i = idx_i[e];

    float4 ex = ((const float4*)g_expl)[e];
    float4 dn = __ldg((const float4*)&g_denom[i * 4]);
    float at[4] = { ex.x / (dn.x + EPSF), ex.y / (dn.y + EPSF),
                    ex.z / (dn.z + EPSF), ex.w / (dn.w + EPSF) };

    float he[32];
    const float4* hb = (const float4*)&g_hedge[(size_t)e * 32];
    #pragma unroll
    for (int q = 0; q < 8; q++) {
        float4 t = hb[q];
        he[4 * q] = t.x; he[4 * q + 1] = t.y; he[4 * q + 2] = t.z; he[4 * q + 3] = t.w;
    }

    u64 mx[16];
    #pragma unroll
    for (int q = 0; q < 16; q++) mx[q] = 0ull;
    #pragma unroll 4
    for (int k = 0; k < 128; k++) {
        float s = at[k >> 5] * he[k & 31];
        u64 s2 = pk2(s);
        const u64* wr = (const u64*)&sWx[k * 32];
        #pragma unroll
        for (int q = 0; q < 16; q++) fma2(mx[q], s2, wr[q]);
    }

    float m[32];
    #pragma unroll
    for (int q = 0; q < 16; q++) {
        float2 p = upk(mx[q]);
        m[2 * q] = tanhf(p.x); m[2 * q + 1] = tanhf(p.y);
    }

    float4 dr = ((const float4*)g_dir)[e];
    float drA[3] = {dr.x, dr.y, dr.z};
    float* cbase = &g_comb[(size_t)i * 96];
    #pragma unroll
    for (int q = 0; q < 24; q++) {
        float v[4];
        #pragma unroll
        for (int s = 0; s < 4; s++) {
            int t = 4 * q + s;
            v[s] = m[t / 3] * drA[t % 3];
        }
        red4(cbase + 4 * q, v[0], v[1], v[2], v[3]);
    }
}

// ---------------- K3: node pass ----------------
__global__ void __launch_bounds__(256, 1) k_node(
    const float* __restrict__ h, const float* __restrict__ xx, const float* __restrict__ vv,
    const float* __restrict__ W1,  const float* __restrict__ b1,
    const float* __restrict__ W2,  const float* __restrict__ b2,
    const float* __restrict__ Wp1, const float* __restrict__ bp1,
    const float* __restrict__ Wp2, const float* __restrict__ bp2,
    const float* __restrict__ Wv1, const float* __restrict__ bv1,
    const float* __restrict__ Wv2, const float* __restrict__ wvm,
    float* __restrict__ out)
{
    extern __shared__ float sw[];
    float* sW1  = sw;              // 224*128 = 28672
    float* sW2  = sw + 28672;      // 128*64  =  8192
    float* sWp1 = sW2 + 8192;      // 32*64   =  2048
    float* sWp2 = sWp1 + 2048;     // 64*32   =  2048
    float* sWv1 = sWp2 + 2048;     // 64*32   =  2048

    {
        float4* d = (float4*)sw;
        const float4* s = (const float4*)W1;
        for (int t = threadIdx.x; t < 28672 / 4; t += 256) d[t] = s[t];
        d = (float4*)sW2; s = (const float4*)W2;
        for (int t = threadIdx.x; t < 8192 / 4; t += 256) d[t] = s[t];
        d = (float4*)sWp1; s = (const float4*)Wp1;
        for (int t = threadIdx.x; t < 2048 / 4; t += 256) d[t] = s[t];
        d = (float4*)sWp2; s = (const float4*)Wp2;
        for (int t = threadIdx.x; t < 2048 / 4; t += 256) d[t] = s[t];
        d = (float4*)sWv1; s = (const float4*)Wv1;
        for (int t = threadIdx.x; t < 2048 / 4; t += 256) d[t] = s[t];
    }
    __syncthreads();

    int i = blockIdx.x * 256 + threadIdx.x;
    if (i >= NN) return;

    // ---- comb (packed 96) -> n2 + dv ----
    float invc = 1.f / fmaxf(g_cnt[i], 1.f);
    float n2[32];
    float dv0 = 0.f, dv1 = 0.f, dv2 = 0.f;
    {
        float val[96];
        const float4* cb = (const float4*)&g_comb[(size_t)i * 96];
        #pragma unroll
        for (int q = 0; q < 24; q++) {
            float4 t = __ldg(&cb[q]);
            val[4 * q] = t.x; val[4 * q + 1] = t.y; val[4 * q + 2] = t.z; val[4 * q + 3] = t.w;
        }
        #pragma unroll
        for (int c = 0; c < 32; c++) {
            float ax = val[3 * c] * invc, ay = val[3 * c + 1] * invc, az = val[3 * c + 2] * invc;
            n2[c] = ax * ax + ay * ay + az * az;
            float w = __ldg(&wvm[c]);
            dv0 += ax * w; dv1 += ay * w; dv2 += az * w;
        }
    }

    // ---- spatial MLP, layer1 -> layer2 fused ----
    float spa[32];
    {
        u64 s2acc[16];
        #pragma unroll
        for (int q = 0; q < 16; q++) s2acc[q] = 0ull;

        #pragma unroll 1
        for (int half = 0; half < 2; half++) {
            u64 acc[16];
            #pragma unroll
            for (int q = 0; q < 16; q++) acc[q] = 0ull;
            #pragma unroll 4
            for (int k = 0; k < 32; k++) {
                u64 nv = pk2(n2[k]);
                const u64* w = (const u64*)&sWp1[k * 64 + half * 32];
                #pragma unroll
                for (int q = 0; q < 16; q++) fma2(acc[q], nv, w[q]);
            }
            #pragma unroll 2
            for (int q = 0; q < 16; q++) {
                float2 p = upk(acc[q]);
                int row = half * 32 + 2 * q;
                float z0 = silu_(p.x + __ldg(&bp1[row]));
                float z1 = silu_(p.y + __ldg(&bp1[row + 1]));
                u64 a0 = pk2(z0), a1 = pk2(z1);
                const u64* w0 = (const u64*)&sWp2[row * 32];
                const u64* w1 = w0 + 16;
                #pragma unroll
                for (int c = 0; c < 16; c++) fma2(s2acc[c], a0, w0[c]);
                #pragma unroll
                for (int c = 0; c < 16; c++) fma2(s2acc[c], a1, w1[c]);
            }
        }
        #pragma unroll
        for (int q = 0; q < 16; q++) {
            float2 p = upk(s2acc[q]);
            spa[2 * q]     = silu_(p.x + __ldg(&bp2[2 * q]));
            spa[2 * q + 1] = silu_(p.y + __ldg(&bp2[2 * q + 1]));
        }
    }

    // ---- sem normalization factors ----
    float4 dn = __ldg((const float4*)&g_denom[i * 4]);
    float inv4[4] = { 1.f / (dn.x + EPSF), 1.f / (dn.y + EPSF),
                      1.f / (dn.z + EPSF), 1.f / (dn.w + EPSF) };

    // ---- node MLP: layer1 (224->128) -> layer2 (128->64) fused ----
    u64 acc2[32];
    #pragma unroll
    for (int q = 0; q < 32; q++) acc2[q] = 0ull;

    const float4* h4 = (const float4*)(h + (size_t)i * 64);
    const float4* s4 = (const float4*)&g_sem[(size_t)i * 128];

    #pragma unroll 1
    for (int half = 0; half < 2; half++) {
        int co = half * 64;
        u64 acc[32];
        #pragma unroll
        for (int q = 0; q < 32; q++) acc[q] = 0ull;

        // h rows 0..63
        #pragma unroll 1
        for (int k4 = 0; k4 < 16; k4++) {
            float4 hv = __ldg(&h4[k4]);
            float hvv[4] = {hv.x, hv.y, hv.z, hv.w};
            #pragma unroll
            for (int u = 0; u < 4; u++) {
                u64 a = pk2(hvv[u]);
                const u64* w = (const u64*)&sW1[(k4 * 4 + u) * 128 + co];
                #pragma unroll
                for (int q = 0; q < 32; q++) fma2(acc[q], a, w[q]);
            }
        }
        // sem rows 64..191 (normalize on load)
        #pragma unroll 1
        for (int k4 = 0; k4 < 32; k4++) {
            float4 sv = __ldg(&s4[k4]);
            float sc = inv4[k4 >> 3];
            float svv[4] = {sv.x * sc, sv.y * sc, sv.z * sc, sv.w * sc};
            #pragma unroll
            for (int u = 0; u < 4; u++) {
                u64 a = pk2(svv[u]);
                const u64* w = (const u64*)&sW1[(64 + k4 * 4 + u) * 128 + co];
                #pragma unroll
                for (int q = 0; q < 32; q++) fma2(acc[q], a, w[q]);
            }
        }
        // spatial rows 192..223
        #pragma unroll 2
        for (int k = 0; k < 32; k++) {
            u64 a = pk2(spa[k]);
            const u64* w = (const u64*)&sW1[(192 + k) * 128 + co];
            #pragma unroll
            for (int q = 0; q < 32; q++) fma2(acc[q], a, w[q]);
        }
        // activation + fused layer2 accumulation
        #pragma unroll 1
        for (int q = 0; q < 32; q++) {
            float2 p = upk(acc[q]);
            int row = co + 2 * q;
            float z0 = silu_(p.x + __ldg(&b1[row]));
            float z1 = silu_(p.y + __ldg(&b1[row + 1]));
            u64 a0 = pk2(z0), a1 = pk2(z1);
            const u64* w0 = (const u64*)&sW2[row * 64];
            const u64* w1 = w0 + 32;
            #pragma unroll
            for (int c = 0; c < 32; c++) fma2(acc2[c], a0, w0[c]);
            #pragma unroll
            for (int c = 0; c < 32; c++) fma2(acc2[c], a1, w1[c]);
        }
    }

    // ---- residual + write h_upd ----
    const float* hr = h + (size_t)i * 64;
    float hu[64];
    #pragma unroll
    for (int q = 0; q < 32; q++) {
        float2 p = upk(acc2[q]);
        hu[2 * q]     = __ldg(&hr[2 * q])     + silu_(p.x + __ldg(&b2[2 * q]));
        hu[2 * q + 1] = __ldg(&hr[2 * q + 1]) + silu_(p.y + __ldg(&b2[2 * q + 1]));
    }
    {
        float4* outh = (float4*)&out[(size_t)i * 64];
        #pragma unroll
        for (int q = 0; q < 16; q++)
            outh[q] = make_float4(hu[4 * q], hu[4 * q + 1], hu[4 * q + 2], hu[4 * q + 3]);
    }

    // ---- gate ----
    float gate;
    {
        u64 ga[16];
        #pragma unroll
        for (int q = 0; q < 16; q++) ga[q] = 0ull;
        #pragma unroll 4
        for (int k = 0; k < 64; k++) {
            u64 a = pk2(hu[k]);
            const u64* w = (const u64*)&sWv1[k * 32];
            #pragma unroll
            for (int q = 0; q < 16; q++) fma2(ga[q], a, w[q]);
        }
        float g = 0.f;
        #pragma unroll
        for (int q = 0; q < 16; q++) {
            float2 p = upk(ga[q]);
            g += silu_(p.x + __ldg(&bv1[2 * q]))     * __ldg(&Wv2[2 * q]);
            g += silu_(p.y + __ldg(&bv1[2 * q + 1])) * __ldg(&Wv2[2 * q + 1]);
        }
        gate = 2.f * (1.f / (1.f + __expf(-g)));
    }

    // ---- v_upd / x_upd ----
    float vx = gate * vv[3 * i]     + dv0;
    float vy = gate * vv[3 * i + 1] + dv1;
    float vz = gate * vv[3 * i + 2] + dv2;
    float* outx = out + (size_t)NN * 64;
    float* outv = outx + (size_t)NN * 3;
    outx[3 * i] = xx[3 * i]     + vx;
    outx[3 * i + 1] = xx[3 * i + 1] + vy;
    outx[3 * i + 2] = xx[3 * i + 2] + vz;
    outv[3 * i] = vx;  outv[3 * i + 1] = vy;  outv[3 * i + 2] = vz;
}

// ---------------- launch ----------------
extern "C" void kernel_launch(void* const* d_in, const int* in_sizes, int n_in,
                              void* d_out, int out_size) {
    const float* h   = (const float*)d_in[0];
    const float* x   = (const float*)d_in[1];
    const float* v   = (const float*)d_in[2];
    const int*   ii  = (const int*)d_in[3];
    const int*   jj  = (const int*)d_in[4];
    const float* Win = (const float*)d_in[5];
    const float* bin = (const float*)d_in[6];
    const float* Wh  = (const float*)d_in[7];
    const float* bh  = (const float*)d_in[8];
    const float* Wo  = (const float*)d_in[9];
    const float* bo  = (const float*)d_in[10];
    const float* Wa  = (const float*)d_in[11];
    const float* ba  = (const float*)d_in[12];
    const float* Wx  = (const float*)d_in[13];
    const float* W1  = (const float*)d_in[14];
    const float* b1  = (const float*)d_in[15];
    const float* W2  = (const float*)d_in[16];
    const float* b2  = (const float*)d_in[17];
    const float* Wp1 = (const float*)d_in[18];
    const float* bp1 = (const float*)d_in[19];
    const float* Wp2 = (const float*)d_in[20];
    const float* bp2 = (const float*)d_in[21];
    const float* Wv1 = (const float*)d_in[22];
    const float* bv1 = (const float*)d_in[23];
    const float* Wv2 = (const float*)d_in[24];
    const float* wvm = (const float*)d_in[25];
    float* out = (float*)d_out;

    const int NODE_SMEM = 43008 * 4;
    cudaFuncSetAttribute(k_node, cudaFuncAttributeMaxDynamicSharedMemorySize, NODE_SMEM);

    k_zero<<<2048, 256>>>();
    k_pre<<<(NN + 255) / 256, 256>>>(h, Wh, Win, bin);
    k_edge1<<<(EE + 255) / 256, 256>>>(x, ii, jj, Wh, bh, Wo, bo, Wa, ba);
    k_edge2<<<(EE + 255) / 256, 256>>>(ii, Wx);
    k_node<<<(NN + 255) / 256, 256, NODE_SMEM>>>(h, x, v, W1, b1, W2, b2, Wp1, bp1, Wp2, bp2,
                                                 Wv1, bv1, Wv2, wvm, out);
}

// round 5
// speedup vs baseline: 1.9019x; 1.0754x over previous
#include <cuda_runtime.h>

#define NN 50000
#define EE 500000
#define EPSF 1e-8f

typedef unsigned long long u64;

// ---------------- scratch (device globals) ----------------
__device__ __align__(16) float g_hedge[EE * 32];
__device__ __align__(16) float g_expl[EE * 4];
__device__ __align__(16) float g_dir[EE * 4];
__device__ __align__(16) float g_denom[NN * 4];
__device__ __align__(16) float g_cnt[NN];
__device__ __align__(16) float g_sem[NN * 128];    // UNNORMALIZED exp*he sums
__device__ __align__(16) float g_comb[NN * 96];    // packed [c*3+axis]
__device__ __align__(16) float g_P1[NN * 64];
__device__ __align__(16) float g_P2[NN * 64];
__device__ __align__(16) float g_Q1[NN * 20];
__device__ __align__(16) float g_Q2[NN * 20];
__device__ __align__(16) float g_spa[NN * 32];     // spatial MLP output
__device__ __align__(16) float g_dv[NN * 4];       // dv.xyz

// ---------------- helpers ----------------
__device__ __forceinline__ u64 pk2(float v) {
    u64 r; asm("mov.b64 %0,{%1,%1};" : "=l"(r) : "f"(v)); return r;
}
__device__ __forceinline__ u64 pk(float a, float b) {
    u64 r; asm("mov.b64 %0,{%1,%2};" : "=l"(r) : "f"(a), "f"(b)); return r;
}
__device__ __forceinline__ void fma2(u64 &d, u64 a, u64 b) {
    asm("fma.rn.f32x2 %0,%1,%2,%0;" : "+l"(d) : "l"(a), "l"(b));
}
__device__ __forceinline__ float2 upk(u64 v) {
    float2 f; asm("mov.b64 {%0,%1},%2;" : "=f"(f.x), "=f"(f.y) : "l"(v)); return f;
}
__device__ __forceinline__ float silu_(float z) { return z * (1.f / (1.f + __expf(-z))); }
__device__ __forceinline__ void red4(float* p, float a, float b, float c, float d) {
    asm volatile("red.global.add.v4.f32 [%0], {%1,%2,%3,%4};"
                 :: "l"(p), "f"(a), "f"(b), "f"(c), "f"(d) : "memory");
}

// ---------------- K0: zero scratch ----------------
__global__ void k_zero() {
    int t = blockIdx.x * blockDim.x + threadIdx.x;
    int stride = gridDim.x * blockDim.x;
    float4 z = make_float4(0.f, 0.f, 0.f, 0.f);
    float4* p1 = (float4*)g_denom;
    for (int q = t; q < NN; q += stride) p1[q] = z;
    float4* p2 = (float4*)g_cnt;
    for (int q = t; q < NN / 4; q += stride) p2[q] = z;
    float4* p3 = (float4*)g_sem;
    for (int q = t; q < NN * 32; q += stride) p3[q] = z;
    float4* p4 = (float4*)g_comb;
    for (int q = t; q < NN * 24; q += stride) p4[q] = z;
}

// ---------------- K_pre: per-node projections ----------------
__global__ void __launch_bounds__(256) k_pre(
    const float* __restrict__ h,
    const float* __restrict__ Wh, const float* __restrict__ Win,
    const float* __restrict__ bin)
{
    __shared__ __align__(16) float sWh[128 * 64];
    __shared__ __align__(16) float sWin[128 * 20];
    for (int t = threadIdx.x; t < 128 * 64; t += 256) sWh[t] = Wh[t];
    for (int t = threadIdx.x; t < 128 * 20; t += 256) sWin[t] = Win[t];
    __syncthreads();

    int i = blockIdx.x * 256 + threadIdx.x;
    if (i >= NN) return;
    const float4* h4 = (const float4*)(h + (size_t)i * 64);

    #pragma unroll 1
    for (int g = 0; g < 2; g++) {
        u64 aP[32]; u64 aQ[10];
        #pragma unroll
        for (int q = 0; q < 32; q++) aP[q] = 0ull;
        #pragma unroll
        for (int q = 0; q < 10; q++) aQ[q] = 0ull;
        #pragma unroll 2
        for (int k4 = 0; k4 < 16; k4++) {
            float4 hv = __ldg(&h4[k4]);
            float hvv[4] = {hv.x, hv.y, hv.z, hv.w};
            #pragma unroll
            for (int u = 0; u < 4; u++) {
                int k = g * 64 + k4 * 4 + u;
                u64 a = pk2(hvv[u]);
                const ulonglong2* wr = (const ulonglong2*)&sWh[k * 64];
                #pragma unroll
                for (int t = 0; t < 16; t++) {
                    ulonglong2 ww = wr[t];
                    fma2(aP[2 * t], a, ww.x); fma2(aP[2 * t + 1], a, ww.y);
                }
                const u64* w2 = (const u64*)&sWin[k * 20];
                #pragma unroll
                for (int q = 0; q < 10; q++) fma2(aQ[q], a, w2[q]);
            }
        }
        float* P = (g == 0) ? &g_P1[(size_t)i * 64] : &g_P2[(size_t)i * 64];
        float* Q = (g == 0) ? &g_Q1[(size_t)i * 20] : &g_Q2[(size_t)i * 20];
        float4* P4 = (float4*)P;
        #pragma unroll
        for (int q = 0; q < 16; q++) {
            float2 p0 = upk(aP[2 * q]);
            float2 p1 = upk(aP[2 * q + 1]);
            P4[q] = make_float4(p0.x, p0.y, p1.x, p1.y);
        }
        #pragma unroll
        for (int q = 0; q < 10; q++) {
            float2 p = upk(aQ[q]);
            if (g == 0) {
                Q[2 * q]     = p.x + __ldg(&bin[2 * q]);
                Q[2 * q + 1] = p.y + __ldg(&bin[2 * q + 1]);
            } else {
                Q[2 * q] = p.x; Q[2 * q + 1] = p.y;
            }
        }
    }
}

// ---------------- K1: edge pass 1 ----------------
__global__ void __launch_bounds__(256) k_edge1(
    const float* __restrict__ xx,
    const int* __restrict__ idx_i, const int* __restrict__ idx_j,
    const float* __restrict__ Wh,  const float* __restrict__ bh,
    const float* __restrict__ Wo,  const float* __restrict__ bo,
    const float* __restrict__ Wa,  const float* __restrict__ ba)
{
    __shared__ __align__(16) float sWr[20 * 64];
    __shared__ __align__(16) float sWl[64];
    __shared__ __align__(16) float sWo[64 * 32];
    __shared__ __align__(16) float sWa[32 * 4];
    __shared__ float sbh[64], sbo[32], sba[4];
    for (int t = threadIdx.x; t < 20 * 64; t += 256) sWr[t] = Wh[128 * 64 + t];
    for (int t = threadIdx.x; t < 64; t += 256)      sWl[t] = Wh[148 * 64 + t];
    for (int t = threadIdx.x; t < 64 * 32; t += 256) sWo[t] = Wo[t];
    for (int t = threadIdx.x; t < 128; t += 256)     sWa[t] = Wa[t];
    if (threadIdx.x < 64) sbh[threadIdx.x] = bh[threadIdx.x];
    if (threadIdx.x < 32) sbo[threadIdx.x] = bo[threadIdx.x];
    if (threadIdx.x < 4)  sba[threadIdx.x] = ba[threadIdx.x];
    __syncthreads();

    int e = blockIdx.x * 256 + threadIdx.x;
    if (e >= EE) return;
    int i = idx_i[e], j = idx_j[e];

    float r0 = __ldg(&xx[3 * j])     - __ldg(&xx[3 * i]);
    float r1 = __ldg(&xx[3 * j + 1]) - __ldg(&xx[3 * i + 1]);
    float r2 = __ldg(&xx[3 * j + 2]) - __ldg(&xx[3 * i + 2]);
    float d  = sqrtf(r0 * r0 + r1 * r1 + r2 * r2 + EPSF);
    float inv = 1.f / (d + EPSF);
    float dir0 = r0 * inv, dir1 = r1 * inv, dir2 = r2 * inv;

    // pre-activation sums from P1[i] + P2[j] (issue these gathers early)
    u64 a64[32];
    {
        const float4* p1 = (const float4*)&g_P1[(size_t)i * 64];
        const float4* p2 = (const float4*)&g_P2[(size_t)j * 64];
        #pragma unroll
        for (int q = 0; q < 16; q++) {
            float4 a = __ldg(&p1[q]);
            float4 b = __ldg(&p2[q]);
            a64[2 * q]     = pk(a.x + b.x, a.y + b.y);
            a64[2 * q + 1] = pk(a.z + b.z, a.w + b.w);
        }
    }

    // RBF filter values
    float f20[20];
    {
        const float4* q1 = (const float4*)&g_Q1[(size_t)i * 20];
        const float4* q2 = (const float4*)&g_Q2[(size_t)j * 20];
        float ed  = __expf(-d);
        const float mu0  = 0.6065306597126334f;
        const float dmu  = (1.f - mu0) / 19.f;
        const float bb   = 0.1f * (1.f - mu0);
        const float beta = 1.f / (bb * bb);
        #pragma unroll
        for (int q = 0; q < 5; q++) {
            float4 a = __ldg(&q1[q]);
            float4 b = __ldg(&q2[q]);
            float qs[4] = {a.x + b.x, a.y + b.y, a.z + b.z, a.w + b.w};
            #pragma unroll
            for (int u = 0; u < 4; u++) {
                int r = q * 4 + u;
                float tt = ed - (mu0 + r * dmu);
                f20[r] = __expf(-beta * tt * tt) * qs[u];
            }
        }
    }

    #pragma unroll 4
    for (int r = 0; r < 20; r++) {
        u64 fv = pk2(f20[r]);
        const ulonglong2* wr = (const ulonglong2*)&sWr[r * 64];
        #pragma unroll
        for (int t = 0; t < 16; t++) {
            ulonglong2 ww = wr[t];
            fma2(a64[2 * t], fv, ww.x); fma2(a64[2 * t + 1], fv, ww.y);
        }
    }
    {
        u64 dv2 = pk2(d);
        const ulonglong2* wr = (const ulonglong2*)sWl;
        #pragma unroll
        for (int t = 0; t < 16; t++) {
            ulonglong2 ww = wr[t];
            fma2(a64[2 * t], dv2, ww.x); fma2(a64[2 * t + 1], dv2, ww.y);
        }
    }

    // bias + silu -> hidden[64]; hidden @ Wo + bo -> he[32]
    u64 ho[16];
    #pragma unroll
    for (int q = 0; q < 16; q++) ho[q] = 0ull;
    #pragma unroll 4
    for (int q = 0; q < 32; q++) {
        float2 p = upk(a64[q]);
        float z0 = silu_(p.x + sbh[2 * q]);
        float z1 = silu_(p.y + sbh[2 * q + 1]);
        u64 h0 = pk2(z0), h1 = pk2(z1);
        const ulonglong2* w0 = (const ulonglong2*)&sWo[(2 * q) * 32];
        const ulonglong2* w1 = (const ulonglong2*)&sWo[(2 * q + 1) * 32];
        #pragma unroll
        for (int t = 0; t < 8; t++) {
            ulonglong2 ww = w0[t];
            fma2(ho[2 * t], h0, ww.x); fma2(ho[2 * t + 1], h0, ww.y);
        }
        #pragma unroll
        for (int t = 0; t < 8; t++) {
            ulonglong2 ww = w1[t];
            fma2(ho[2 * t], h1, ww.x); fma2(ho[2 * t + 1], h1, ww.y);
        }
    }
    float he[32];
    #pragma unroll
    for (int q = 0; q < 16; q++) {
        float2 p = upk(ho[q]);
        he[2 * q]     = p.x + sbo[2 * q];
        he[2 * q + 1] = p.y + sbo[2 * q + 1];
    }

    float4* st = (float4*)&g_hedge[(size_t)e * 32];
    #pragma unroll
    for (int q = 0; q < 8; q++)
        st[q] = make_float4(he[4 * q], he[4 * q + 1], he[4 * q + 2], he[4 * q + 3]);

    // logits -> celu(alpha=2) -> exp
    float l0 = sba[0], l1 = sba[1], l2 = sba[2], l3 = sba[3];
    const float4* wa4 = (const float4*)sWa;
    #pragma unroll
    for (int c = 0; c < 32; c++) {
        float4 w = wa4[c];
        l0 += he[c] * w.x; l1 += he[c] * w.y; l2 += he[c] * w.z; l3 += he[c] * w.w;
    }
    float eArr[4];
    eArr[0] = __expf(l0 > 0.f ? l0 : 2.f * (__expf(0.5f * l0) - 1.f));
    eArr[1] = __expf(l1 > 0.f ? l1 : 2.f * (__expf(0.5f * l1) - 1.f));
    eArr[2] = __expf(l2 > 0.f ? l2 : 2.f * (__expf(0.5f * l2) - 1.f));
    eArr[3] = __expf(l3 > 0.f ? l3 : 2.f * (__expf(0.5f * l3) - 1.f));

    ((float4*)g_expl)[e] = make_float4(eArr[0], eArr[1], eArr[2], eArr[3]);
    ((float4*)g_dir)[e]  = make_float4(dir0, dir1, dir2, d);
    red4(&g_denom[i * 4], eArr[0], eArr[1], eArr[2], eArr[3]);
    atomicAdd(&g_cnt[i], 1.f);

    float* sembase = &g_sem[(size_t)i * 128];
    #pragma unroll
    for (int kk = 0; kk < 32; kk++) {
        float eh = eArr[kk >> 3];
        int b0 = (4 * kk) & 31;
        red4(sembase + 4 * kk, eh * he[b0], eh * he[b0 + 1], eh * he[b0 + 2], eh * he[b0 + 3]);
    }
}

// ---------------- K2: edge pass 2 (unchanged) ----------------
__global__ void __launch_bounds__(256) k_edge2(
    const int* __restrict__ idx_i, const float* __restrict__ Wx)
{
    __shared__ __align__(16) float sWx[128 * 32];
    for (int t = threadIdx.x; t < 128 * 32; t += 256) sWx[t] = Wx[t];
    __syncthreads();

    int e = blockIdx.x * 256 + threadIdx.x;
    if (e >= EE) return;
    int i = idx_i[e];

    float4 ex = ((const float4*)g_expl)[e];
    float4 dn = __ldg((const float4*)&g_denom[i * 4]);
    float at[4] = { ex.x / (dn.x + EPSF), ex.y / (dn.y + EPSF),
                    ex.z / (dn.z + EPSF), ex.w / (dn.w + EPSF) };

    float he[32];
    const float4* hb = (const float4*)&g_hedge[(size_t)e * 32];
    #pragma unroll
    for (int q = 0; q < 8; q++) {
        float4 t = hb[q];
        he[4 * q] = t.x; he[4 * q + 1] = t.y; he[4 * q + 2] = t.z; he[4 * q + 3] = t.w;
    }

    u64 mx[16];
    #pragma unroll
    for (int q = 0; q < 16; q++) mx[q] = 0ull;
    #pragma unroll 4
    for (int k = 0; k < 128; k++) {
        float s = at[k >> 5] * he[k & 31];
        u64 s2 = pk2(s);
        const ulonglong2* wr = (const ulonglong2*)&sWx[k * 32];
        #pragma unroll
        for (int t = 0; t < 8; t++) {
            ulonglong2 ww = wr[t];
            fma2(mx[2 * t], s2, ww.x); fma2(mx[2 * t + 1], s2, ww.y);
        }
    }

    float m[32];
    #pragma unroll
    for (int q = 0; q < 16; q++) {
        float2 p = upk(mx[q]);
        m[2 * q] = tanhf(p.x); m[2 * q + 1] = tanhf(p.y);
    }

    float4 dr = ((const float4*)g_dir)[e];
    float drA[3] = {dr.x, dr.y, dr.z};
    float* cbase = &g_comb[(size_t)i * 96];
    #pragma unroll
    for (int q = 0; q < 24; q++) {
        float v[4];
        #pragma unroll
        for (int s = 0; s < 4; s++) {
            int t = 4 * q + s;
            v[s] = m[t / 3] * drA[t % 3];
        }
        red4(cbase + 4 * q, v[0], v[1], v[2], v[3]);
    }
}

// ---------------- K3a: spatial MLP + dv ----------------
__global__ void __launch_bounds__(256) k_spatial(
    const float* __restrict__ Wp1, const float* __restrict__ bp1,
    const float* __restrict__ Wp2, const float* __restrict__ bp2,
    const float* __restrict__ wvm)
{
    __shared__ __align__(16) float sWp1[32 * 64];
    __shared__ __align__(16) float sWp2[64 * 32];
    __shared__ float sbp1[64], sbp2[32], swv[32];
    for (int t = threadIdx.x; t < 2048; t += 256) sWp1[t] = Wp1[t];
    for (int t = threadIdx.x; t < 2048; t += 256) sWp2[t] = Wp2[t];
    if (threadIdx.x < 64) sbp1[threadIdx.x] = bp1[threadIdx.x];
    if (threadIdx.x < 32) sbp2[threadIdx.x] = bp2[threadIdx.x];
    if (threadIdx.x < 32) swv[threadIdx.x] = wvm[threadIdx.x];
    __syncthreads();

    int i = blockIdx.x * 256 + threadIdx.x;
    if (i >= NN) return;

    float invc = 1.f / fmaxf(g_cnt[i], 1.f);
    float n2[32];
    float dv0 = 0.f, dv1 = 0.f, dv2 = 0.f;
    {
        float val[96];
        const float4* cb = (const float4*)&g_comb[(size_t)i * 96];
        #pragma unroll
        for (int q = 0; q < 24; q++) {
            float4 t = __ldg(&cb[q]);
            val[4 * q] = t.x; val[4 * q + 1] = t.y; val[4 * q + 2] = t.z; val[4 * q + 3] = t.w;
        }
        #pragma unroll
        for (int c = 0; c < 32; c++) {
            float ax = val[3 * c] * invc, ay = val[3 * c + 1] * invc, az = val[3 * c + 2] * invc;
            n2[c] = ax * ax + ay * ay + az * az;
            float w = swv[c];
            dv0 += ax * w; dv1 += ay * w; dv2 += az * w;
        }
    }

    u64 s2acc[16];
    #pragma unroll
    for (int q = 0; q < 16; q++) s2acc[q] = 0ull;

    #pragma unroll 1
    for (int half = 0; half < 2; half++) {
        u64 acc[16];
        #pragma unroll
        for (int q = 0; q < 16; q++) acc[q] = 0ull;
        #pragma unroll 4
        for (int k = 0; k < 32; k++) {
            u64 nv = pk2(n2[k]);
            const ulonglong2* w = (const ulonglong2*)&sWp1[k * 64 + half * 32];
            #pragma unroll
            for (int t = 0; t < 8; t++) {
                ulonglong2 ww = w[t];
                fma2(acc[2 * t], nv, ww.x); fma2(acc[2 * t + 1], nv, ww.y);
            }
        }
        #pragma unroll 2
        for (int q = 0; q < 16; q++) {
            float2 p = upk(acc[q]);
            int row = half * 32 + 2 * q;
            float z0 = silu_(p.x + sbp1[row]);
            float z1 = silu_(p.y + sbp1[row + 1]);
            u64 a0 = pk2(z0), a1 = pk2(z1);
            const ulonglong2* w0 = (const ulonglong2*)&sWp2[row * 32];
            const ulonglong2* w1 = (const ulonglong2*)&sWp2[(row + 1) * 32];
            #pragma unroll
            for (int t = 0; t < 8; t++) {
                ulonglong2 ww = w0[t];
                fma2(s2acc[2 * t], a0, ww.x); fma2(s2acc[2 * t + 1], a0, ww.y);
            }
            #pragma unroll
            for (int t = 0; t < 8; t++) {
                ulonglong2 ww = w1[t];
                fma2(s2acc[2 * t], a1, ww.x); fma2(s2acc[2 * t + 1], a1, ww.y);
            }
        }
    }
    float4* sp4 = (float4*)&g_spa[(size_t)i * 32];
    #pragma unroll
    for (int q = 0; q < 8; q++) {
        float2 p0 = upk(s2acc[2 * q]);
        float2 p1 = upk(s2acc[2 * q + 1]);
        sp4[q] = make_float4(silu_(p0.x + sbp2[4 * q]),     silu_(p0.y + sbp2[4 * q + 1]),
                             silu_(p1.x + sbp2[4 * q + 2]), silu_(p1.y + sbp2[4 * q + 3]));
    }
    ((float4*)g_dv)[i] = make_float4(dv0, dv1, dv2, 0.f);
}

// ---------------- K3b: node MLP + gate + outputs ----------------
// 512 threads, <=128 regs, 16 warps/SM, grid=98 (single wave)
__global__ void __launch_bounds__(512, 1) k_nodemlp(
    const float* __restrict__ h, const float* __restrict__ xx, const float* __restrict__ vv,
    const float* __restrict__ W1,  const float* __restrict__ b1,
    const float* __restrict__ W2,  const float* __restrict__ b2,
    const float* __restrict__ Wv1, const float* __restrict__ bv1,
    const float* __restrict__ Wv2,
    float* __restrict__ out)
{
    extern __shared__ __align__(16) float sw[];
    float* sW1  = sw;                 // 224*128 = 28672 f
    float* sW2  = sw + 28672;         // 128*64  =  8192 f
    float* sWv1 = sW2 + 8192;         //  64*32  =  2048 f
    float* sb1  = sWv1 + 2048;        // 128
    float* sb2  = sb1 + 128;          // 64
    float* sbv1 = sb2 + 64;           // 32
    float* sWv2 = sbv1 + 32;          // 32

    {
        float4* d = (float4*)sW1;
        const float4* s = (const float4*)W1;
        for (int t = threadIdx.x; t < 28672 / 4; t += 512) d[t] = s[t];
        d = (float4*)sW2; s = (const float4*)W2;
        for (int t = threadIdx.x; t < 8192 / 4; t += 512) d[t] = s[t];
        d = (float4*)sWv1; s = (const float4*)Wv1;
        for (int t = threadIdx.x; t < 2048 / 4; t += 512) d[t] = s[t];
        if (threadIdx.x < 128) sb1[threadIdx.x] = b1[threadIdx.x];
        if (threadIdx.x < 64)  sb2[threadIdx.x] = b2[threadIdx.x];
        if (threadIdx.x < 32)  sbv1[threadIdx.x] = bv1[threadIdx.x];
        if (threadIdx.x < 32)  sWv2[threadIdx.x] = Wv2[threadIdx.x];
    }
    __syncthreads();

    int i = blockIdx.x * 512 + threadIdx.x;
    if (i >= NN) return;

    float4 dn = __ldg((const float4*)&g_denom[i * 4]);
    float inv4[4] = { 1.f / (dn.x + EPSF), 1.f / (dn.y + EPSF),
                      1.f / (dn.z + EPSF), 1.f / (dn.w + EPSF) };

    const float4* hs = (const float4*)(h + (size_t)i * 64);
    const float4* ss = (const float4*)&g_sem[(size_t)i * 128];
    const float4* ps = (const float4*)&g_spa[(size_t)i * 32];

    u64 acc2[32];
    #pragma unroll
    for (int q = 0; q < 32; q++) acc2[q] = 0ull;

    #pragma unroll 1
    for (int qtr = 0; qtr < 4; qtr++) {
        int co = qtr * 32;
        u64 acc[16];
        #pragma unroll
        for (int q = 0; q < 16; q++) acc[q] = 0ull;

        // --- h rows 0..63 (prefetch 1-ahead) ---
        {
            float4 cur = __ldg(&hs[0]);
            #pragma unroll 1
            for (int k4 = 0; k4 < 16; k4++) {
                float4 nxt = (k4 < 15) ? __ldg(&hs[k4 + 1]) : make_float4(0.f, 0.f, 0.f, 0.f);
                float av[4] = {cur.x, cur.y, cur.z, cur.w};
                #pragma unroll
                for (int u = 0; u < 4; u++) {
                    u64 a = pk2(av[u]);
                    const ulonglong2* w = (const ulonglong2*)&sW1[(k4 * 4 + u) * 128 + co];
                    #pragma unroll
                    for (int t = 0; t < 8; t++) {
                        ulonglong2 ww = w[t];
                        fma2(acc[2 * t], a, ww.x); fma2(acc[2 * t + 1], a, ww.y);
                    }
                }
                cur = nxt;
            }
        }
        // --- sem rows 64..191 (normalize on load) ---
        {
            float4 cur = __ldg(&ss[0]);
            #pragma unroll 1
            for (int k4 = 0; k4 < 32; k4++) {
                float4 nxt = (k4 < 31) ? __ldg(&ss[k4 + 1]) : make_float4(0.f, 0.f, 0.f, 0.f);
                float sc = inv4[k4 >> 3];
                float av[4] = {cur.x * sc, cur.y * sc, cur.z * sc, cur.w * sc};
                #pragma unroll
                for (int u = 0; u < 4; u++) {
                    u64 a = pk2(av[u]);
                    const ulonglong2* w = (const ulonglong2*)&sW1[(64 + k4 * 4 + u) * 128 + co];
                    #pragma unroll
                    for (int t = 0; t < 8; t++) {
                        ulonglong2 ww = w[t];
                        fma2(acc[2 * t], a, ww.x); fma2(acc[2 * t + 1], a, ww.y);
                    }
                }
                cur = nxt;
            }
        }
        // --- spa rows 192..223 ---
        {
            float4 cur = __ldg(&ps[0]);
            #pragma unroll 1
            for (int k4 = 0; k4 < 8; k4++) {
                float4 nxt = (k4 < 7) ? __ldg(&ps[k4 + 1]) : make_float4(0.f, 0.f, 0.f, 0.f);
                float av[4] = {cur.x, cur.y, cur.z, cur.w};
                #pragma unroll
                for (int u = 0; u < 4; u++) {
                    u64 a = pk2(av[u]);
                    const ulonglong2* w = (const ulonglong2*)&sW1[(192 + k4 * 4 + u) * 128 + co];
                    #pragma unroll
                    for (int t = 0; t < 8; t++) {
                        ulonglong2 ww = w[t];
                        fma2(acc[2 * t], a, ww.x); fma2(acc[2 * t + 1], a, ww.y);
                    }
                }
                cur = nxt;
            }
        }
        // --- activation + fused W2 accumulation ---
        #pragma unroll 1
        for (int q = 0; q < 16; q++) {
            float2 p = upk(acc[q]);
            int row = co + 2 * q;
            float z0 = silu_(p.x + sb1[row]);
            float z1 = silu_(p.y + sb1[row + 1]);
            u64 a0 = pk2(z0), a1 = pk2(z1);
            const ulonglong2* w0 = (const ulonglong2*)&sW2[row * 64];
            const ulonglong2* w1 = (const ulonglong2*)&sW2[(row + 1) * 64];
            #pragma unroll
            for (int t = 0; t < 16; t++) {
                ulonglong2 ww = w0[t];
                fma2(acc2[2 * t], a0, ww.x); fma2(acc2[2 * t + 1], a0, ww.y);
            }
            #pragma unroll
            for (int t = 0; t < 16; t++) {
                ulonglong2 ww = w1[t];
                fma2(acc2[2 * t], a1, ww.x); fma2(acc2[2 * t + 1], a1, ww.y);
            }
        }
    }

    // ---- residual + write h_upd + fused gate matvec ----
    const float* hr = h + (size_t)i * 64;
    float2* outh = (float2*)&out[(size_t)i * 64];
    u64 ga[16];
    #pragma unroll
    for (int q = 0; q < 16; q++) ga[q] = 0ull;

    #pragma unroll 1
    for (int q = 0; q < 32; q++) {
        float2 p = upk(acc2[q]);
        float hu0 = __ldg(&hr[2 * q])     + silu_(p.x + sb2[2 * q]);
        float hu1 = __ldg(&hr[2 * q + 1]) + silu_(p.y + sb2[2 * q + 1]);
        outh[q] = make_float2(hu0, hu1);
        u64 a0 = pk2(hu0), a1 = pk2(hu1);
        const ulonglong2* w0 = (const ulonglong2*)&sWv1[(2 * q) * 32];
        const ulonglong2* w1 = (const ulonglong2*)&sWv1[(2 * q + 1) * 32];
        #pragma unroll
        for (int t = 0; t < 8; t++) {
            ulonglong2 ww = w0[t];
            fma2(ga[2 * t], a0, ww.x); fma2(ga[2 * t + 1], a0, ww.y);
        }
        #pragma unroll
        for (int t = 0; t < 8; t++) {
            ulonglong2 ww = w1[t];
            fma2(ga[2 * t], a1, ww.x); fma2(ga[2 * t + 1], a1, ww.y);
        }
    }

    float g = 0.f;
    #pragma unroll
    for (int q = 0; q < 16; q++) {
        float2 p = upk(ga[q]);
        g += silu_(p.x + sbv1[2 * q])     * sWv2[2 * q];
        g += silu_(p.y + sbv1[2 * q + 1]) * sWv2[2 * q + 1];
    }
    float gate = 2.f * (1.f / (1.f + __expf(-g)));

    float4 dv = __ldg((const float4*)&g_dv[i * 4]);
    float vx = gate * vv[3 * i]     + dv.x;
    float vy = gate * vv[3 * i + 1] + dv.y;
    float vz = gate * vv[3 * i + 2] + dv.z;
    float* outx = out + (size_t)NN * 64;
    float* outv = outx + (size_t)NN * 3;
    outx[3 * i]     = xx[3 * i]     + vx;
    outx[3 * i + 1] = xx[3 * i + 1] + vy;
    outx[3 * i + 2] = xx[3 * i + 2] + vz;
    outv[3 * i] = vx;  outv[3 * i + 1] = vy;  outv[3 * i + 2] = vz;
}

// ---------------- launch ----------------
extern "C" void kernel_launch(void* const* d_in, const int* in_sizes, int n_in,
                              void* d_out, int out_size) {
    const float* h   = (const float*)d_in[0];
    const float* x   = (const float*)d_in[1];
    const float* v   = (const float*)d_in[2];
    const int*   ii  = (const int*)d_in[3];
    const int*   jj  = (const int*)d_in[4];
    const float* Win = (const float*)d_in[5];
    const float* bin = (const float*)d_in[6];
    const float* Wh  = (const float*)d_in[7];
    const float* bh  = (const float*)d_in[8];
    const float* Wo  = (const float*)d_in[9];
    const float* bo  = (const float*)d_in[10];
    const float* Wa  = (const float*)d_in[11];
    const float* ba  = (const float*)d_in[12];
    const float* Wx  = (const float*)d_in[13];
    const float* W1  = (const float*)d_in[14];
    const float* b1  = (const float*)d_in[15];
    const float* W2  = (const float*)d_in[16];
    const float* b2  = (const float*)d_in[17];
    const float* Wp1 = (const float*)d_in[18];
    const float* bp1 = (const float*)d_in[19];
    const float* Wp2 = (const float*)d_in[20];
    const float* bp2 = (const float*)d_in[21];
    const float* Wv1 = (const float*)d_in[22];
    const float* bv1 = (const float*)d_in[23];
    const float* Wv2 = (const float*)d_in[24];
    const float* wvm = (const float*)d_in[25];
    float* out = (float*)d_out;

    const int NODE_SMEM = (28672 + 8192 + 2048 + 128 + 64 + 32 + 32) * 4;  // 156,672 B
    cudaFuncSetAttribute(k_nodemlp, cudaFuncAttributeMaxDynamicSharedMemorySize, NODE_SMEM);

    k_zero<<<2048, 256>>>();
    k_pre<<<(NN + 255) / 256, 256>>>(h, Wh, Win, bin);
    k_edge1<<<(EE + 255) / 256, 256>>>(x, ii, jj, Wh, bh, Wo, bo, Wa, ba);
    k_edge2<<<(EE + 255) / 256, 256>>>(ii, Wx);
    k_spatial<<<(NN + 255) / 256, 256>>>(Wp1, bp1, Wp2, bp2, wvm);
    k_nodemlp<<<(NN + 511) / 512, 512, NODE_SMEM>>>(h, x, v, W1, b1, W2, b2,
                                                    Wv1, bv1, Wv2, out);
}